// round 10
// baseline (speedup 1.0000x reference)
#include <cuda_runtime.h>
#include <math.h>

#define NB 4
#define NS 512
#define NDIM 512
#define NH 8
#define NDH 64
#define NM (NB*NS)     // 2048

// ---------------- device scratch (no allocations allowed) ----------------
__device__ float g_q[NB*NH*NS*NDH];     // [b][h][s][d]
__device__ float g_k[NB*NH*NS*NDH];
__device__ float g_v[NB*NH*NS*NDH];
__device__ float g_u[NB*NS*NH];
__device__ float g_w[NB*NH*NS];
__device__ float g_opos[NB*NH*NDH];     // [b][h][d] : w @ V
__device__ float g_y[NM*NDIM];

// tf32 hi/lo pre-split fragment arrays (dense GEMMs)
__device__ float g_xh[NM*NDIM], g_xl[NM*NDIM];
__device__ float g_yh[NM*NDIM], g_yl[NM*NDIM];
__device__ float g_wh[4*NDIM*NDIM], g_wl[4*NDIM*NDIM];
// attention fragment arrays
// Q A-side: [bh][mblk(32)][kblk(8)][lane(32)][reg(4)]
__device__ float g_qfh[NB*NH*NS*NDH], g_qfl[NB*NH*NS*NDH];
// K B-side: [bh][kblk(8 dims)][nblk(64 pos)][lane(32)][reg(2)]
__device__ float g_kfh[NB*NH*NS*NDH], g_kfl[NB*NH*NS*NDH];
// V B-side: [bh][kposblk(64)][nblk(8 dh)][lane(32)][reg(2)]
__device__ float g_vfh[NB*NH*NS*NDH], g_vfl[NB*NH*NS*NDH];

__device__ __forceinline__ unsigned f2tf(float x) {
    unsigned r;
    asm("cvt.rna.tf32.f32 %0, %1;" : "=r"(r) : "f"(x));
    return r;
}

__device__ __forceinline__ void mma_tf32(float (&d)[4], const unsigned (&a)[4],
                                         unsigned b0, unsigned b1) {
    asm volatile(
        "mma.sync.aligned.m16n8k8.row.col.f32.tf32.tf32.f32 "
        "{%0,%1,%2,%3}, {%4,%5,%6,%7}, {%8,%9}, {%0,%1,%2,%3};"
        : "+f"(d[0]), "+f"(d[1]), "+f"(d[2]), "+f"(d[3])
        : "r"(a[0]), "r"(a[1]), "r"(a[2]), "r"(a[3]), "r"(b0), "r"(b1));
}

__device__ __forceinline__ unsigned cvta_sh(const void* p) {
    return (unsigned)__cvta_generic_to_shared(p);
}
#define CPA16(dst, src) \
    asm volatile("cp.async.cg.shared.global [%0], [%1], 16;" :: "r"(dst), "l"(src))

// ---------------- coalesced split kernels (dense GEMM operands) ----------
__device__ __forceinline__ void split_a2(const float* __restrict__ src,
                                         float* __restrict__ dh, float* __restrict__ dl) {
    int gw = blockIdx.x * 8 + (threadIdx.x >> 5);
    int lane = threadIdx.x & 31;
    int mblk = gw >> 6, kblk = gw & 63;
    float h[4], l[4];
    #pragma unroll
    for (int r = 0; r < 4; r++) {
        int mr = (lane >> 2) | ((r & 1) << 3);
        int kc = (lane & 3) | ((r >> 1) << 2);
        float v = src[(mblk * 16 + mr) * NDIM + kblk * 8 + kc];
        h[r] = __uint_as_float(f2tf(v));
        l[r] = __uint_as_float(f2tf(v - h[r]));
    }
    int idx = (gw * 32 + lane) * 4;
    *(float4*)&dh[idx] = make_float4(h[0], h[1], h[2], h[3]);
    *(float4*)&dl[idx] = make_float4(l[0], l[1], l[2], l[3]);
}
__global__ void split_x_kernel(const float* __restrict__ X) { split_a2(X, g_xh, g_xl); }
__global__ void split_y_kernel() { split_a2(g_y, g_yh, g_yl); }

__global__ void split_w_kernel(const float* __restrict__ Wq, const float* __restrict__ Wk,
                               const float* __restrict__ Wv, const float* __restrict__ Wo) {
    int gw = blockIdx.x * 8 + (threadIdx.x >> 5);
    int lane = threadIdx.x & 31;
    int mat = gw >> 12;
    int rem = gw & 4095;
    int kblk = rem >> 6, nblk = rem & 63;
    const float* W = (mat == 0) ? Wq : (mat == 1) ? Wk : (mat == 2) ? Wv : Wo;
    int nc = lane >> 2, tl = lane & 3;
    float h[2], l[2];
    #pragma unroll
    for (int r = 0; r < 2; r++) {
        int kc = tl | (r << 2);
        float v = W[(kblk * 8 + kc) * NDIM + nblk * 8 + nc];
        h[r] = __uint_as_float(f2tf(v));
        l[r] = __uint_as_float(f2tf(v - h[r]));
    }
    int idx = mat * NDIM * NDIM + (rem * 32 + lane) * 2;
    *(float2*)&g_wh[idx] = make_float2(h[0], h[1]);
    *(float2*)&g_wl[idx] = make_float2(l[0], l[1]);
}

// ---------------- attention fragment splits ----------------
__global__ void split_q_kernel() {
    int gw = blockIdx.x * 8 + (threadIdx.x >> 5);   // 0..8191
    int lane = threadIdx.x & 31;
    int bh = gw >> 8, rem = gw & 255;
    int mblk = rem >> 3, kblk = rem & 7;
    const float* Q = g_q + (size_t)bh * NS * NDH;
    int g = lane >> 2, t = lane & 3;
    float h[4], l[4];
    #pragma unroll
    for (int r = 0; r < 4; r++) {
        int mr = g | ((r & 1) << 3);
        int kc = t | ((r >> 1) << 2);
        float v = Q[(mblk * 16 + mr) * NDH + kblk * 8 + kc];
        h[r] = __uint_as_float(f2tf(v));
        l[r] = __uint_as_float(f2tf(v - h[r]));
    }
    size_t idx = ((size_t)gw * 32 + lane) * 4;
    *(float4*)&g_qfh[idx] = make_float4(h[0], h[1], h[2], h[3]);
    *(float4*)&g_qfl[idx] = make_float4(l[0], l[1], l[2], l[3]);
}

__global__ void split_kv_kernel() {
    int gw = blockIdx.x * 8 + (threadIdx.x >> 5);   // 0..16383
    int lane = threadIdx.x & 31;
    int nc = lane >> 2, t = lane & 3;
    int bh = gw >> 9, rem = gw & 511;
    if (blockIdx.y == 0) {
        int kblk = rem >> 6, nblk = rem & 63;
        const float* K = g_k + (size_t)bh * NS * NDH;
        float h[2], l[2];
        #pragma unroll
        for (int r = 0; r < 2; r++) {
            float v = K[(nblk * 8 + nc) * NDH + kblk * 8 + t + 4 * r];
            h[r] = __uint_as_float(f2tf(v));
            l[r] = __uint_as_float(f2tf(v - h[r]));
        }
        size_t idx = ((size_t)gw * 32 + lane) * 2;
        *(float2*)&g_kfh[idx] = make_float2(h[0], h[1]);
        *(float2*)&g_kfl[idx] = make_float2(l[0], l[1]);
    } else {
        int kposblk = rem >> 3, nblk = rem & 7;
        const float* V = g_v + (size_t)bh * NS * NDH;
        float h[2], l[2];
        #pragma unroll
        for (int r = 0; r < 2; r++) {
            float v = V[(kposblk * 8 + t + 4 * r) * NDH + nblk * 8 + nc];
            h[r] = __uint_as_float(f2tf(v));
            l[r] = __uint_as_float(f2tf(v - h[r]));
        }
        size_t idx = ((size_t)gw * 32 + lane) * 2;
        *(float2*)&g_vfh[idx] = make_float2(h[0], h[1]);
        *(float2*)&g_vfl[idx] = make_float2(l[0], l[1]);
    }
}

// =====================================================================
// tf32 x3 MMA GEMM, 128x128 tile, 8 warps.
// k16 stages, 3 smem buffers, single barrier/stage, 2 stages in flight.
// buffer layout (floats): Ah[2048] Al[2048] Bh[2048] Bl[2048] = 8192
// =====================================================================
#define GEMM_SMEM_FLOATS (3 * 8192)
#define GEMM_SMEM_BYTES  (GEMM_SMEM_FLOATS * 4)   // 98304

__device__ __forceinline__ void mma_gemm_tile3(const float* __restrict__ Ah,
                                               const float* __restrict__ Al,
                                               const float* __restrict__ Bh,
                                               const float* __restrict__ Bl,
                                               int mblk0, int nblk0,
                                               float (&acc)[2][8][4], float* sm) {
    int tid = threadIdx.x, lane = tid & 31, wid = tid >> 5;
    int warp_m = wid >> 1, warp_n = wid & 1;

    // A loader: 8 mblk x 32 lanes, 8 floats (2x16B) per array per lane
    int a_mb = tid >> 5;
    int a_off = (tid & 31) * 8;
    const float* srcAh = Ah + (size_t)(mblk0 + a_mb) * 8192 + a_off;   // + s*256
    const float* srcAl = Al + (size_t)(mblk0 + a_mb) * 8192 + a_off;
    // B loader: flat 2048 floats/stage, 8 per thread
    int b_idx = tid * 8;
    int b_kbl = b_idx >> 10;
    int b_rem = b_idx & 1023;
    const float* srcBh = Bh + (size_t)b_kbl * 4096 + (size_t)nblk0 * 64 + b_rem; // + s*8192
    const float* srcBl = Bl + (size_t)b_kbl * 4096 + (size_t)nblk0 * 64 + b_rem;

    auto issue = [&](int s) {
        float* base = sm + (s % 3) * 8192;
        unsigned d0 = cvta_sh(base + a_mb * 256 + a_off);
        CPA16(d0,      srcAh + s * 256);
        CPA16(d0 + 16, srcAh + s * 256 + 4);
        unsigned d1 = cvta_sh(base + 2048 + a_mb * 256 + a_off);
        CPA16(d1,      srcAl + s * 256);
        CPA16(d1 + 16, srcAl + s * 256 + 4);
        unsigned d2 = cvta_sh(base + 4096 + b_kbl * 1024 + b_rem);
        CPA16(d2,      srcBh + (size_t)s * 8192);
        CPA16(d2 + 16, srcBh + (size_t)s * 8192 + 4);
        unsigned d3 = cvta_sh(base + 6144 + b_kbl * 1024 + b_rem);
        CPA16(d3,      srcBl + (size_t)s * 8192);
        CPA16(d3 + 16, srcBl + (size_t)s * 8192 + 4);
        asm volatile("cp.async.commit_group;");
    };

    issue(0);
    issue(1);
    for (int s = 0; s < 32; s++) {
        if (s < 31) asm volatile("cp.async.wait_group 1;");
        else        asm volatile("cp.async.wait_group 0;");
        __syncthreads();
        if (s < 30) issue(s + 2);
        float* base = sm + (s % 3) * 8192;
        #pragma unroll
        for (int kbl = 0; kbl < 2; kbl++) {
            unsigned ah[2][4], al[2][4];
            #pragma unroll
            for (int mb2 = 0; mb2 < 2; mb2++) {
                float4 h4 = *(float4*)(base + (warp_m * 2 + mb2) * 256 + kbl * 128 + lane * 4);
                float4 l4 = *(float4*)(base + 2048 + (warp_m * 2 + mb2) * 256 + kbl * 128 + lane * 4);
                ah[mb2][0] = __float_as_uint(h4.x); ah[mb2][1] = __float_as_uint(h4.y);
                ah[mb2][2] = __float_as_uint(h4.z); ah[mb2][3] = __float_as_uint(h4.w);
                al[mb2][0] = __float_as_uint(l4.x); al[mb2][1] = __float_as_uint(l4.y);
                al[mb2][2] = __float_as_uint(l4.z); al[mb2][3] = __float_as_uint(l4.w);
            }
            #pragma unroll
            for (int nb = 0; nb < 8; nb++) {
                float2 h2 = *(float2*)(base + 4096 + kbl * 1024 + (warp_n * 8 + nb) * 64 + lane * 2);
                float2 l2 = *(float2*)(base + 6144 + kbl * 1024 + (warp_n * 8 + nb) * 64 + lane * 2);
                unsigned b0h = __float_as_uint(h2.x), b1h = __float_as_uint(h2.y);
                unsigned b0l = __float_as_uint(l2.x), b1l = __float_as_uint(l2.y);
                #pragma unroll
                for (int mb2 = 0; mb2 < 2; mb2++) {
                    mma_tf32(acc[mb2][nb], ah[mb2], b0h, b1h);
                    mma_tf32(acc[mb2][nb], ah[mb2], b0l, b1l);
                    mma_tf32(acc[mb2][nb], al[mb2], b0h, b1h);
                }
            }
        }
    }
}

__global__ void __launch_bounds__(256, 2)
qkv_mma() {
    extern __shared__ float gsm[];
    int mat = blockIdx.z;
    float* out = (mat == 0) ? g_q : (mat == 1) ? g_k : g_v;
    const float* Bh = g_wh + mat * NDIM * NDIM;
    const float* Bl = g_wl + mat * NDIM * NDIM;
    int m0 = blockIdx.y * 128, n0 = blockIdx.x * 128;
    float acc[2][8][4] = {};
    mma_gemm_tile3(g_xh, g_xl, Bh, Bl, m0 >> 4, n0 >> 3, acc, gsm);

    int lane = threadIdx.x & 31, wid = threadIdx.x >> 5;
    int warp_m = wid >> 1, warp_n = wid & 1;
    int g = lane >> 2, t = lane & 3;
    #pragma unroll
    for (int mb2 = 0; mb2 < 2; mb2++) {
        int mrow = m0 + warp_m * 32 + mb2 * 16 + g;
        #pragma unroll
        for (int nb = 0; nb < 8; nb++) {
            int ncol = n0 + (warp_n * 8 + nb) * 8 + 2 * t;
            int h = ncol >> 6, d = ncol & 63;
            {
                int b = mrow >> 9, s = mrow & 511;
                *(float2*)&out[((b * NH + h) * NS + s) * NDH + d] =
                    make_float2(acc[mb2][nb][0], acc[mb2][nb][1]);
            }
            {
                int m2 = mrow + 8;
                int b = m2 >> 9, s = m2 & 511;
                *(float2*)&out[((b * NH + h) * NS + s) * NDH + d] =
                    make_float2(acc[mb2][nb][2], acc[mb2][nb][3]);
            }
        }
    }
}

__global__ void __launch_bounds__(256, 2)
out_mma(const float* __restrict__ bo, float* __restrict__ out) {
    extern __shared__ float gsm[];
    const float* Bh = g_wh + 3 * NDIM * NDIM;
    const float* Bl = g_wl + 3 * NDIM * NDIM;
    int m0 = blockIdx.y * 128, n0 = blockIdx.x * 128;
    float acc[2][8][4] = {};
    mma_gemm_tile3(g_yh, g_yl, Bh, Bl, m0 >> 4, n0 >> 3, acc, gsm);

    int lane = threadIdx.x & 31, wid = threadIdx.x >> 5;
    int warp_m = wid >> 1, warp_n = wid & 1;
    int g = lane >> 2, t = lane & 3;
    #pragma unroll
    for (int mb2 = 0; mb2 < 2; mb2++) {
        int mrow = m0 + warp_m * 32 + mb2 * 16 + g;
        #pragma unroll
        for (int nb = 0; nb < 8; nb++) {
            int ncol = n0 + (warp_n * 8 + nb) * 8 + 2 * t;
            float b0 = bo[ncol], b1 = bo[ncol + 1];
            *(float2*)&out[(size_t)mrow * NDIM + ncol] =
                make_float2(acc[mb2][nb][0] + b0, acc[mb2][nb][1] + b1);
            *(float2*)&out[(size_t)(mrow + 8) * NDIM + ncol] =
                make_float2(acc[mb2][nb][2] + b0, acc[mb2][nb][3] + b1);
        }
    }
}

// ---------------- tiny positional MLP ----------------
__global__ void u_kernel(const float* __restrict__ pos,
                         const float* __restrict__ Wp1, const float* __restrict__ bp1,
                         const float* __restrict__ Wp2, const float* __restrict__ bp2,
                         const float* __restrict__ Wh) {
    int idx = blockIdx.x * blockDim.x + threadIdx.x;
    if (idx >= NM) return;
    g_opos[idx & (NB*NH*NDH - 1)] = 0.0f;
    const float* pp = pos + idx * 3;
    float p0 = pp[0], p1 = pp[1], p2 = pp[2];
    float h1[3];
    #pragma unroll
    for (int j = 0; j < 3; j++)
        h1[j] = fmaxf(0.0f, p0 * Wp1[j] + p1 * Wp1[3 + j] + p2 * Wp1[6 + j] + bp1[j]);
    float u[NH];
    #pragma unroll
    for (int hh = 0; hh < NH; hh++) u[hh] = 0.0f;
    for (int j = 0; j < 64; j++) {
        float pv = h1[0] * Wp2[j] + h1[1] * Wp2[64 + j] + h1[2] * Wp2[128 + j] + bp2[j];
        #pragma unroll
        for (int hh = 0; hh < NH; hh++) u[hh] += pv * Wh[j * NH + hh];
    }
    #pragma unroll
    for (int hh = 0; hh < NH; hh++) g_u[idx * NH + hh] = u[hh];
}

__global__ void pos_w_kernel() {
    __shared__ float red[512];
    int bh = blockIdx.x;
    int b = bh >> 3, h = bh & 7;
    int k = threadIdx.x;
    float t = -g_u[(b * NS + k) * NH + h];
    red[k] = t; __syncthreads();
    for (int s = 256; s > 0; s >>= 1) { if (k < s) red[k] = fmaxf(red[k], red[k + s]); __syncthreads(); }
    float m = red[0]; __syncthreads();
    float e = expf(t - m);
    red[k] = e; __syncthreads();
    for (int s = 256; s > 0; s >>= 1) { if (k < s) red[k] += red[k + s]; __syncthreads(); }
    g_w[bh * NS + k] = e / red[0];
}

__global__ void opos_kernel() {
    __shared__ float part[4][64];
    int bh = blockIdx.x;
    int kq = blockIdx.y;
    int d = threadIdx.x & 63;
    int ks = threadIdx.x >> 6;
    const float* V = g_v + (size_t)bh * NS * NDH;
    const float* w = g_w + bh * NS;
    int kbase = kq * 128 + ks * 32;
    float s = 0.0f;
    #pragma unroll 4
    for (int k = kbase; k < kbase + 32; k++)
        s += w[k] * V[k * NDH + d];
    part[ks][d] = s;
    __syncthreads();
    if (threadIdx.x < 64)
        atomicAdd(&g_opos[bh * NDH + d], part[0][d] + part[1][d] + part[2][d] + part[3][d]);
}

// =====================================================================
// tf32 mma flash attention v3: K and V staged in separate cp.async
// groups so loads overlap compute (K(kc+1) covered by softmax+PV,
// V(kc+1) covered by next QK).
// =====================================================================
#define ATTN_SMEM_FLOATS (16384 + 64*68 + 64)
#define ATTN_SMEM_BYTES  (ATTN_SMEM_FLOATS * 4)

__global__ void __launch_bounds__(128, 2)
attn_mma(const float* __restrict__ gate) {
    extern __shared__ float asm_[];
    float* sKh = asm_;
    float* sKl = asm_ + 4096;
    float* sVh = asm_ + 8192;
    float* sVl = asm_ + 12288;
    float (*Ps)[68] = (float(*)[68])(asm_ + 16384);
    float* opos_s = asm_ + 16384 + 64 * 68;

    int tid = threadIdx.x, lane = tid & 31, w = tid >> 5;
    int bh = blockIdx.y, q0 = blockIdx.x * 64;
    int h = bh & 7, b = bh >> 3;
    int g = lane >> 2, t = lane & 3;
    int mblk = (q0 >> 4) + w;
    int rowbase = w * 16;

    float gv = 1.0f / (1.0f + __expf(-gate[h]));
    float og = 1.0f - gv;
    if (tid < 64) opos_s[tid] = g_opos[bh * NDH + tid];

    const float* kfh = g_kfh + (size_t)bh * 32768;
    const float* kfl = g_kfl + (size_t)bh * 32768;
    const float* vfh = g_vfh + (size_t)bh * 32768;
    const float* vfl = g_vfl + (size_t)bh * 32768;

    auto stage_K = [&](int kc) {
        #pragma unroll
        for (int r = 0; r < 8; r++) {
            int i = (r * 128 + tid) * 4;
            int kb = i >> 9, rem = i & 511;
            size_t koff = (size_t)(kb * 64 + kc * 8) * 64 + rem;
            CPA16(cvta_sh(&sKh[i]), kfh + koff);
            CPA16(cvta_sh(&sKl[i]), kfl + koff);
        }
        asm volatile("cp.async.commit_group;");
    };
    auto stage_V = [&](int kc) {
        #pragma unroll
        for (int r = 0; r < 8; r++) {
            int i = (r * 128 + tid) * 4;
            size_t voff = (size_t)kc * 4096 + i;
            CPA16(cvta_sh(&sVh[i]), vfh + voff);
            CPA16(cvta_sh(&sVl[i]), vfl + voff);
        }
        asm volatile("cp.async.commit_group;");
    };

    // Q fragments hoisted
    unsigned aqh[8][4], aql[8][4];
    {
        const float* qh = g_qfh + ((size_t)(bh * 32 + mblk) * 8) * 128;
        const float* ql = g_qfl + ((size_t)(bh * 32 + mblk) * 8) * 128;
        #pragma unroll
        for (int kb = 0; kb < 8; kb++) {
            float4 hv = *(const float4*)&qh[kb * 128 + lane * 4];
            float4 lv = *(const float4*)&ql[kb * 128 + lane * 4];
            aqh[kb][0] = __float_as_uint(hv.x); aqh[kb][1] = __float_as_uint(hv.y);
            aqh[kb][2] = __float_as_uint(hv.z); aqh[kb][3] = __float_as_uint(hv.w);
            aql[kb][0] = __float_as_uint(lv.x); aql[kb][1] = __float_as_uint(lv.y);
            aql[kb][2] = __float_as_uint(lv.z); aql[kb][3] = __float_as_uint(lv.w);
        }
    }

    stage_K(0);
    stage_V(0);

    float o[8][4] = {};
    float mrow[2] = {-1e30f, -1e30f};
    float lrow[2] = {0.0f, 0.0f};

    for (int kc = 0; kc < 8; kc++) {
        // K(kc) ready (oldest group); V(kc) may still be in flight
        asm volatile("cp.async.wait_group 1;");
        __syncthreads();

        // ---- S chunk = Q K^T, 3-split tf32, K from smem ----
        float sacc[8][4] = {};
        #pragma unroll
        for (int kb = 0; kb < 8; kb++) {
            #pragma unroll
            for (int nb = 0; nb < 8; nb++) {
                int off = (kb * 512 + nb * 64) + lane * 2;
                float2 h2 = *(float2*)&sKh[off];
                float2 l2 = *(float2*)&sKl[off];
                unsigned b0h = __float_as_uint(h2.x), b1h = __float_as_uint(h2.y);
                unsigned b0l = __float_as_uint(l2.x), b1l = __float_as_uint(l2.y);
                mma_tf32(sacc[nb], aqh[kb], b0h, b1h);
                mma_tf32(sacc[nb], aqh[kb], b0l, b1l);
                mma_tf32(sacc[nb], aql[kb], b0h, b1h);
            }
        }
        __syncthreads();                  // all warps done reading K
        if (kc < 7) stage_K(kc + 1);      // overlap with softmax + PV

        // ---- online softmax (registers only) ----
        #pragma unroll
        for (int j = 0; j < 2; j++) {
            float mx = -1e30f;
            #pragma unroll
            for (int nb = 0; nb < 8; nb++)
                mx = fmaxf(mx, fmaxf(sacc[nb][2*j], sacc[nb][2*j+1]));
            mx *= 0.125f;
            mx = fmaxf(mx, __shfl_xor_sync(0xFFFFFFFF, mx, 1));
            mx = fmaxf(mx, __shfl_xor_sync(0xFFFFFFFF, mx, 2));
            float mn = fmaxf(mrow[j], mx);
            float alpha = __expf(mrow[j] - mn);
            float rs = 0.0f;
            #pragma unroll
            for (int nb = 0; nb < 8; nb++) {
                float p0 = __expf(sacc[nb][2*j] * 0.125f - mn);
                float p1 = __expf(sacc[nb][2*j+1] * 0.125f - mn);
                sacc[nb][2*j] = p0; sacc[nb][2*j+1] = p1;
                rs += p0 + p1;
            }
            rs += __shfl_xor_sync(0xFFFFFFFF, rs, 1);
            rs += __shfl_xor_sync(0xFFFFFFFF, rs, 2);
            lrow[j] = lrow[j] * alpha + rs;
            mrow[j] = mn;
            #pragma unroll
            for (int nb = 0; nb < 8; nb++) { o[nb][2*j] *= alpha; o[nb][2*j+1] *= alpha; }
        }

        // V(kc) ready: outstanding = {V(kc), K(kc+1)} (or just {V(7)})
        if (kc < 7) asm volatile("cp.async.wait_group 1;");
        else        asm volatile("cp.async.wait_group 0;");
        __syncthreads();

        // ---- P c-layout -> warp-private smem strip ----
        #pragma unroll
        for (int nb = 0; nb < 8; nb++) {
            *(float2*)&Ps[rowbase + g][nb * 8 + 2 * t]     = make_float2(sacc[nb][0], sacc[nb][1]);
            *(float2*)&Ps[rowbase + g + 8][nb * 8 + 2 * t] = make_float2(sacc[nb][2], sacc[nb][3]);
        }
        __syncwarp();
        // ---- O += P @ V (3-split), V from smem ----
        #pragma unroll
        for (int kb = 0; kb < 8; kb++) {
            float p0 = Ps[rowbase + g][kb * 8 + t];
            float p1 = Ps[rowbase + g + 8][kb * 8 + t];
            float p2 = Ps[rowbase + g][kb * 8 + t + 4];
            float p3 = Ps[rowbase + g + 8][kb * 8 + t + 4];
            unsigned ph[4], pl[4];
            ph[0] = f2tf(p0); pl[0] = f2tf(p0 - __uint_as_float(ph[0]));
            ph[1] = f2tf(p1); pl[1] = f2tf(p1 - __uint_as_float(ph[1]));
            ph[2] = f2tf(p2); pl[2] = f2tf(p2 - __uint_as_float(ph[2]));
            ph[3] = f2tf(p3); pl[3] = f2tf(p3 - __uint_as_float(ph[3]));
            #pragma unroll
            for (int nb = 0; nb < 8; nb++) {
                int off = (kb * 512 + nb * 64) + lane * 2;
                float2 h2 = *(float2*)&sVh[off];
                float2 l2 = *(float2*)&sVl[off];
                unsigned b0h = __float_as_uint(h2.x), b1h = __float_as_uint(h2.y);
                unsigned b0l = __float_as_uint(l2.x), b1l = __float_as_uint(l2.y);
                mma_tf32(o[nb], ph, b0h, b1h);
                mma_tf32(o[nb], ph, b0l, b1l);
                mma_tf32(o[nb], pl, b0h, b1h);
            }
        }
        __syncthreads();                  // all warps done reading V
        if (kc < 7) stage_V(kc + 1);      // overlap with next QK
    }

    // ---- epilogue: out = og * o / l + gv * O_pos ----
    #pragma unroll
    for (int j = 0; j < 2; j++) {
        int q = q0 + rowbase + g + j * 8;
        float f = og / lrow[j];
        #pragma unroll
        for (int nb = 0; nb < 8; nb++) {
            int d = nb * 8 + 2 * t;
            *(float2*)&g_y[((size_t)b * NS + q) * NDIM + h * NDH + d] =
                make_float2(o[nb][2*j] * f + gv * opos_s[d],
                            o[nb][2*j+1] * f + gv * opos_s[d + 1]);
        }
    }
}

extern "C" void kernel_launch(void* const* d_in, const int* in_sizes, int n_in,
                              void* d_out, int out_size) {
    const float* x    = (const float*)d_in[0];
    const float* pos  = (const float*)d_in[1];
    const float* Wq   = (const float*)d_in[2];
    const float* Wk   = (const float*)d_in[3];
    const float* Wv   = (const float*)d_in[4];
    const float* Wo   = (const float*)d_in[5];
    const float* bo   = (const float*)d_in[6];
    const float* Wp1  = (const float*)d_in[7];
    const float* bp1  = (const float*)d_in[8];
    const float* Wp2  = (const float*)d_in[9];
    const float* bp2  = (const float*)d_in[10];
    const float* Wh   = (const float*)d_in[11];
    // d_in[12] = bh : cancels inside softmax — unused
    const float* gate = (const float*)d_in[13];
    float* out = (float*)d_out;

    static bool attr_set = false;
    if (!attr_set) {
        cudaFuncSetAttribute(attn_mma, cudaFuncAttributeMaxDynamicSharedMemorySize, ATTN_SMEM_BYTES);
        cudaFuncSetAttribute(qkv_mma, cudaFuncAttributeMaxDynamicSharedMemorySize, GEMM_SMEM_BYTES);
        cudaFuncSetAttribute(out_mma, cudaFuncAttributeMaxDynamicSharedMemorySize, GEMM_SMEM_BYTES);
        attr_set = true;
    }

    u_kernel<<<8, 256>>>(pos, Wp1, bp1, Wp2, bp2, Wh);
    pos_w_kernel<<<32, 512>>>();
    split_w_kernel<<<2048, 256>>>(Wq, Wk, Wv, Wo);
    split_x_kernel<<<1024, 256>>>(x);
    qkv_mma<<<dim3(4, 16, 3), 256, GEMM_SMEM_BYTES>>>();
    split_q_kernel<<<1024, 256>>>();
    split_kv_kernel<<<dim3(2048, 2), 256>>>();
    opos_kernel<<<dim3(32, 4), 256>>>();
    attn_mma<<<dim3(8, 32), 128, ATTN_SMEM_BYTES>>>(gate);
    split_y_kernel<<<1024, 256>>>();
    out_mma<<<dim3(4, 16), 256, GEMM_SMEM_BYTES>>>(bo, out);
}

// round 12
// speedup vs baseline: 1.7709x; 1.7709x over previous
#include <cuda_runtime.h>
#include <cuda_bf16.h>
#include <math.h>

#define NB 4
#define NS 512
#define NDIM 512
#define NH 8
#define NDH 64
#define NM (NB*NS)     // 2048

// ---------------- device scratch (no allocations allowed) ----------------
__device__ float g_q[NB*NH*NS*NDH];     // [b][h][s][d]
__device__ float g_k[NB*NH*NS*NDH];
__device__ float g_v[NB*NH*NS*NDH];
__device__ float g_u[NB*NS*NH];
__device__ float g_w[NB*NH*NS];
__device__ float g_opos[NB*NH*NDH];     // [b][h][d] : w @ V
__device__ float g_y[NM*NDIM];

// bf16 hi/lo packed fragment arrays (each u32 = bf16x2, low half = even-k elem)
// Dense A-side (X or y): [mblk(128)][kblk(32)][lane(32)][reg(4)] = 524288 u32
__device__ unsigned g_xh[NM*NDIM/2], g_xl[NM*NDIM/2];
__device__ unsigned g_yh[NM*NDIM/2], g_yl[NM*NDIM/2];
// Dense B-side (W): per mat [kblk(32)][nblk(64)][lane(32)][reg(2)] = 131072 u32/mat
__device__ unsigned g_wh[4*NDIM*NDIM/2], g_wl[4*NDIM*NDIM/2];
#define WMAT_STRIDE (NDIM*NDIM/2)       // 131072
// Q A-side: [bh(32)][mblk(32)][kblk(4)][lane(32)][reg(4)] = 16384 u32/bh
__device__ unsigned g_qfh[NB*NH*NS*NDH/2], g_qfl[NB*NH*NS*NDH/2];
// K B-side: [bh][kblk(4 dim16)][nblk(64 pos8)][lane][reg(2)] = 16384 u32/bh
__device__ unsigned g_kfh[NB*NH*NS*NDH/2], g_kfl[NB*NH*NS*NDH/2];
// V B-side: [bh][kposblk(32)][nblk(8 dh8)][lane][reg(2)] = 16384 u32/bh
__device__ unsigned g_vfh[NB*NH*NS*NDH/2], g_vfl[NB*NH*NS*NDH/2];

__device__ __forceinline__ float bf16f(float x) {
    return __bfloat162float(__float2bfloat16_rn(x));
}
// pack (even-k elem e0 -> low half, odd-k e1 -> high half)
__device__ __forceinline__ unsigned pk2(float e0, float e1) {
    unsigned r;
    asm("cvt.rn.bf16x2.f32 %0, %1, %2;" : "=r"(r) : "f"(e1), "f"(e0));
    return r;
}

__device__ __forceinline__ void mma_bf16(float (&d)[4], const unsigned (&a)[4],
                                         unsigned b0, unsigned b1) {
    asm volatile(
        "mma.sync.aligned.m16n8k16.row.col.f32.bf16.bf16.f32 "
        "{%0,%1,%2,%3}, {%4,%5,%6,%7}, {%8,%9}, {%0,%1,%2,%3};"
        : "+f"(d[0]), "+f"(d[1]), "+f"(d[2]), "+f"(d[3])
        : "r"(a[0]), "r"(a[1]), "r"(a[2]), "r"(a[3]), "r"(b0), "r"(b1));
}

__device__ __forceinline__ unsigned cvta_sh(const void* p) {
    return (unsigned)__cvta_generic_to_shared(p);
}
#define CPA16(dst, src) \
    asm volatile("cp.async.cg.shared.global [%0], [%1], 16;" :: "r"(dst), "l"(src))

// ---------------- split kernels ----------------
// A-side dense: warp per (mblk,kblk16); lane -> uint4 per array.
__device__ __forceinline__ void split_a_bf(const float* __restrict__ src,
                                           unsigned* __restrict__ dh,
                                           unsigned* __restrict__ dl) {
    int gw = blockIdx.x * 8 + (threadIdx.x >> 5);   // 0..4095
    int lane = threadIdx.x & 31;
    int mblk = gw >> 5, kblk = gw & 31;
    int g = lane >> 2, t = lane & 3;
    unsigned hr[4], lr[4];
    #pragma unroll
    for (int r = 0; r < 4; r++) {
        int row = mblk * 16 + g + (r & 1) * 8;
        int col = kblk * 16 + 2 * t + (r >> 1) * 8;
        float2 v = *(const float2*)&src[row * NDIM + col];
        float h0 = bf16f(v.x), h1 = bf16f(v.y);
        hr[r] = pk2(h0, h1);
        lr[r] = pk2(v.x - h0, v.y - h1);
    }
    size_t idx = ((size_t)gw * 32 + lane) * 4;
    *(uint4*)&dh[idx] = make_uint4(hr[0], hr[1], hr[2], hr[3]);
    *(uint4*)&dl[idx] = make_uint4(lr[0], lr[1], lr[2], lr[3]);
}
__global__ void split_x_kernel(const float* __restrict__ X) { split_a_bf(X, g_xh, g_xl); }
__global__ void split_y_kernel() { split_a_bf(g_y, g_yh, g_yl); }

// B-side dense: warp per (mat,kblk16,nblk8)
__global__ void split_w_kernel(const float* __restrict__ Wq, const float* __restrict__ Wk,
                               const float* __restrict__ Wv, const float* __restrict__ Wo) {
    int gw = blockIdx.x * 8 + (threadIdx.x >> 5);   // 0..8191
    int lane = threadIdx.x & 31;
    int mat = gw >> 11, rem = gw & 2047;
    const float* W = (mat == 0) ? Wq : (mat == 1) ? Wk : (mat == 2) ? Wv : Wo;
    int kblk = rem >> 6, nblk = rem & 63;
    int g = lane >> 2, t = lane & 3;
    unsigned hr[2], lr[2];
    #pragma unroll
    for (int r = 0; r < 2; r++) {
        int k = kblk * 16 + 2 * t + r * 8;
        int n = nblk * 8 + g;
        float v0 = W[k * NDIM + n], v1 = W[(k + 1) * NDIM + n];
        float h0 = bf16f(v0), h1 = bf16f(v1);
        hr[r] = pk2(h0, h1);
        lr[r] = pk2(v0 - h0, v1 - h1);
    }
    size_t idx = (size_t)mat * WMAT_STRIDE + ((size_t)rem * 32 + lane) * 2;
    *(uint2*)&g_wh[idx] = make_uint2(hr[0], hr[1]);
    *(uint2*)&g_wl[idx] = make_uint2(lr[0], lr[1]);
}

// Q A-side: warp per (bh, mblk, kblk4)
__global__ void split_q_kernel() {
    int gw = blockIdx.x * 8 + (threadIdx.x >> 5);   // 0..4095
    int lane = threadIdx.x & 31;
    int bh = gw >> 7, rem = gw & 127;
    int mblk = rem >> 2, kblk = rem & 3;
    const float* Q = g_q + (size_t)bh * NS * NDH;
    int g = lane >> 2, t = lane & 3;
    unsigned hr[4], lr[4];
    #pragma unroll
    for (int r = 0; r < 4; r++) {
        int row = mblk * 16 + g + (r & 1) * 8;
        int col = kblk * 16 + 2 * t + (r >> 1) * 8;
        float2 v = *(const float2*)&Q[row * NDH + col];
        float h0 = bf16f(v.x), h1 = bf16f(v.y);
        hr[r] = pk2(h0, h1);
        lr[r] = pk2(v.x - h0, v.y - h1);
    }
    size_t idx = ((size_t)gw * 32 + lane) * 4;
    *(uint4*)&g_qfh[idx] = make_uint4(hr[0], hr[1], hr[2], hr[3]);
    *(uint4*)&g_qfl[idx] = make_uint4(lr[0], lr[1], lr[2], lr[3]);
}

// K/V B-side: warp per (bh, 256 sub-ids); y=0 -> K, y=1 -> V
__global__ void split_kv_kernel() {
    int gw = blockIdx.x * 8 + (threadIdx.x >> 5);   // 0..8191
    int lane = threadIdx.x & 31;
    int g = lane >> 2, t = lane & 3;
    int bh = gw >> 8, rem = gw & 255;
    unsigned hr[2], lr[2];
    if (blockIdx.y == 0) {
        // K: kblk(4 dim16) x nblk(64 pos8); value K[pos=n][dim=k]
        int kblk = rem >> 6, nblk = rem & 63;
        const float* K = g_k + (size_t)bh * NS * NDH;
        #pragma unroll
        for (int r = 0; r < 2; r++) {
            int k = kblk * 16 + 2 * t + r * 8;    // dim
            int n = nblk * 8 + g;                 // kpos
            float2 v = *(const float2*)&K[n * NDH + k];
            float h0 = bf16f(v.x), h1 = bf16f(v.y);
            hr[r] = pk2(h0, h1);
            lr[r] = pk2(v.x - h0, v.y - h1);
        }
        size_t idx = ((size_t)gw * 32 + lane) * 2;   // [bh][kblk][nblk][lane][2]
        *(uint2*)&g_kfh[idx] = make_uint2(hr[0], hr[1]);
        *(uint2*)&g_kfl[idx] = make_uint2(lr[0], lr[1]);
    } else {
        // V: kposblk(32) x nblk(8 dh8); value V[kpos=k][dh=n]
        int kpb = rem >> 3, nblk = rem & 7;
        const float* V = g_v + (size_t)bh * NS * NDH;
        #pragma unroll
        for (int r = 0; r < 2; r++) {
            int k = kpb * 16 + 2 * t + r * 8;     // kpos
            int n = nblk * 8 + g;                 // dh
            float v0 = V[k * NDH + n], v1 = V[(k + 1) * NDH + n];
            float h0 = bf16f(v0), h1 = bf16f(v1);
            hr[r] = pk2(h0, h1);
            lr[r] = pk2(v0 - h0, v1 - h1);
        }
        size_t idx = ((size_t)gw * 32 + lane) * 2;   // [bh][kpb][nblk][lane][2]
        *(uint2*)&g_vfh[idx] = make_uint2(hr[0], hr[1]);
        *(uint2*)&g_vfl[idx] = make_uint2(lr[0], lr[1]);
    }
}

// =====================================================================
// bf16 x3 MMA GEMM, 128x128 tile, 8 warps, k16 stages, 3 smem buffers.
// Stage = 4096 u32: Ah[1024] Al[1024] Bh[1024] Bl[1024] = 16KB
// =====================================================================
#define GEMM_SMEM_BYTES (3 * 4096 * 4)   // 49152

__device__ __forceinline__ void mma_gemm_bf16(const unsigned* __restrict__ Ah,
                                              const unsigned* __restrict__ Al,
                                              const unsigned* __restrict__ Bh,
                                              const unsigned* __restrict__ Bl,
                                              int mblk0, int nblk0,
                                              float (&acc)[2][8][4], unsigned* sm) {
    int tid = threadIdx.x, lane = tid & 31, wid = tid >> 5;
    int warp_m = wid >> 1, warp_n = wid & 1;
    int a_mb = tid >> 5, a_ln = tid & 31;
    int b_nb = tid >> 4, b_j = tid & 15;

    // A: per mblk 4096 u32 (32 kblk x 128); stage s adds 128
    const unsigned* srcAh = Ah + (size_t)(mblk0 + a_mb) * 4096 + a_ln * 4;
    const unsigned* srcAl = Al + (size_t)(mblk0 + a_mb) * 4096 + a_ln * 4;
    // B: per kblk 4096 u32 (64 nblk x 64); stage s adds 4096
    const unsigned* srcBh = Bh + (size_t)(nblk0 + b_nb) * 64 + b_j * 4;
    const unsigned* srcBl = Bl + (size_t)(nblk0 + b_nb) * 64 + b_j * 4;

    auto issue = [&](int s) {
        unsigned* base = sm + (s % 3) * 4096;
        CPA16(cvta_sh(base + a_mb * 128 + a_ln * 4),        srcAh + s * 128);
        CPA16(cvta_sh(base + 1024 + a_mb * 128 + a_ln * 4), srcAl + s * 128);
        CPA16(cvta_sh(base + 2048 + b_nb * 64 + b_j * 4),   srcBh + (size_t)s * 4096);
        CPA16(cvta_sh(base + 3072 + b_nb * 64 + b_j * 4),   srcBl + (size_t)s * 4096);
        asm volatile("cp.async.commit_group;");
    };

    issue(0);
    issue(1);
    for (int s = 0; s < 32; s++) {
        if (s < 31) asm volatile("cp.async.wait_group 1;");
        else        asm volatile("cp.async.wait_group 0;");
        __syncthreads();
        if (s < 30) issue(s + 2);
        unsigned* base = sm + (s % 3) * 4096;
        unsigned ah[2][4], al[2][4];
        #pragma unroll
        for (int mb2 = 0; mb2 < 2; mb2++) {
            uint4 h4 = *(uint4*)(base + (warp_m * 2 + mb2) * 128 + lane * 4);
            uint4 l4 = *(uint4*)(base + 1024 + (warp_m * 2 + mb2) * 128 + lane * 4);
            ah[mb2][0] = h4.x; ah[mb2][1] = h4.y; ah[mb2][2] = h4.z; ah[mb2][3] = h4.w;
            al[mb2][0] = l4.x; al[mb2][1] = l4.y; al[mb2][2] = l4.z; al[mb2][3] = l4.w;
        }
        #pragma unroll
        for (int nb = 0; nb < 8; nb++) {
            uint2 bh2 = *(uint2*)(base + 2048 + (warp_n * 8 + nb) * 64 + lane * 2);
            uint2 bl2 = *(uint2*)(base + 3072 + (warp_n * 8 + nb) * 64 + lane * 2);
            #pragma unroll
            for (int mb2 = 0; mb2 < 2; mb2++) {
                mma_bf16(acc[mb2][nb], ah[mb2], bh2.x, bh2.y);
                mma_bf16(acc[mb2][nb], ah[mb2], bl2.x, bl2.y);
                mma_bf16(acc[mb2][nb], al[mb2], bh2.x, bh2.y);
            }
        }
    }
}

__global__ void __launch_bounds__(256, 2)
qkv_mma() {
    extern __shared__ unsigned gsm[];
    int mat = blockIdx.z;
    float* out = (mat == 0) ? g_q : (mat == 1) ? g_k : g_v;
    const unsigned* Bh = g_wh + (size_t)mat * WMAT_STRIDE;
    const unsigned* Bl = g_wl + (size_t)mat * WMAT_STRIDE;
    int m0 = blockIdx.y * 128, n0 = blockIdx.x * 128;
    float acc[2][8][4] = {};
    mma_gemm_bf16(g_xh, g_xl, Bh, Bl, m0 >> 4, n0 >> 3, acc, gsm);

    int lane = threadIdx.x & 31, wid = threadIdx.x >> 5;
    int warp_m = wid >> 1, warp_n = wid & 1;
    int g = lane >> 2, t = lane & 3;
    #pragma unroll
    for (int mb2 = 0; mb2 < 2; mb2++) {
        int mrow = m0 + warp_m * 32 + mb2 * 16 + g;
        #pragma unroll
        for (int nb = 0; nb < 8; nb++) {
            int ncol = n0 + (warp_n * 8 + nb) * 8 + 2 * t;
            int h = ncol >> 6, d = ncol & 63;
            {
                int b = mrow >> 9, s = mrow & 511;
                *(float2*)&out[((b * NH + h) * NS + s) * NDH + d] =
                    make_float2(acc[mb2][nb][0], acc[mb2][nb][1]);
            }
            {
                int m2 = mrow + 8;
                int b = m2 >> 9, s = m2 & 511;
                *(float2*)&out[((b * NH + h) * NS + s) * NDH + d] =
                    make_float2(acc[mb2][nb][2], acc[mb2][nb][3]);
            }
        }
    }
}

__global__ void __launch_bounds__(256, 2)
out_mma(const float* __restrict__ bo, float* __restrict__ out) {
    extern __shared__ unsigned gsm[];
    const unsigned* Bh = g_wh + (size_t)3 * WMAT_STRIDE;
    const unsigned* Bl = g_wl + (size_t)3 * WMAT_STRIDE;
    int m0 = blockIdx.y * 128, n0 = blockIdx.x * 128;
    float acc[2][8][4] = {};
    mma_gemm_bf16(g_yh, g_yl, Bh, Bl, m0 >> 4, n0 >> 3, acc, gsm);

    int lane = threadIdx.x & 31, wid = threadIdx.x >> 5;
    int warp_m = wid >> 1, warp_n = wid & 1;
    int g = lane >> 2, t = lane & 3;
    #pragma unroll
    for (int mb2 = 0; mb2 < 2; mb2++) {
        int mrow = m0 + warp_m * 32 + mb2 * 16 + g;
        #pragma unroll
        for (int nb = 0; nb < 8; nb++) {
            int ncol = n0 + (warp_n * 8 + nb) * 8 + 2 * t;
            float b0 = bo[ncol], b1 = bo[ncol + 1];
            *(float2*)&out[(size_t)mrow * NDIM + ncol] =
                make_float2(acc[mb2][nb][0] + b0, acc[mb2][nb][1] + b1);
            *(float2*)&out[(size_t)(mrow + 8) * NDIM + ncol] =
                make_float2(acc[mb2][nb][2] + b0, acc[mb2][nb][3] + b1);
        }
    }
}

// ---------------- tiny positional MLP ----------------
__global__ void u_kernel(const float* __restrict__ pos,
                         const float* __restrict__ Wp1, const float* __restrict__ bp1,
                         const float* __restrict__ Wp2, const float* __restrict__ bp2,
                         const float* __restrict__ Wh) {
    int idx = blockIdx.x * blockDim.x + threadIdx.x;
    if (idx >= NM) return;
    g_opos[idx & (NB*NH*NDH - 1)] = 0.0f;
    const float* pp = pos + idx * 3;
    float p0 = pp[0], p1 = pp[1], p2 = pp[2];
    float h1[3];
    #pragma unroll
    for (int j = 0; j < 3; j++)
        h1[j] = fmaxf(0.0f, p0 * Wp1[j] + p1 * Wp1[3 + j] + p2 * Wp1[6 + j] + bp1[j]);
    float u[NH];
    #pragma unroll
    for (int hh = 0; hh < NH; hh++) u[hh] = 0.0f;
    for (int j = 0; j < 64; j++) {
        float pv = h1[0] * Wp2[j] + h1[1] * Wp2[64 + j] + h1[2] * Wp2[128 + j] + bp2[j];
        #pragma unroll
        for (int hh = 0; hh < NH; hh++) u[hh] += pv * Wh[j * NH + hh];
    }
    #pragma unroll
    for (int hh = 0; hh < NH; hh++) g_u[idx * NH + hh] = u[hh];
}

__global__ void pos_w_kernel() {
    __shared__ float red[512];
    int bh = blockIdx.x;
    int b = bh >> 3, h = bh & 7;
    int k = threadIdx.x;
    float t = -g_u[(b * NS + k) * NH + h];
    red[k] = t; __syncthreads();
    for (int s = 256; s > 0; s >>= 1) { if (k < s) red[k] = fmaxf(red[k], red[k + s]); __syncthreads(); }
    float m = red[0]; __syncthreads();
    float e = expf(t - m);
    red[k] = e; __syncthreads();
    for (int s = 256; s > 0; s >>= 1) { if (k < s) red[k] += red[k + s]; __syncthreads(); }
    g_w[bh * NS + k] = e / red[0];
}

__global__ void opos_kernel() {
    __shared__ float part[4][64];
    int bh = blockIdx.x;
    int kq = blockIdx.y;
    int d = threadIdx.x & 63;
    int ks = threadIdx.x >> 6;
    const float* V = g_v + (size_t)bh * NS * NDH;
    const float* w = g_w + bh * NS;
    int kbase = kq * 128 + ks * 32;
    float s = 0.0f;
    #pragma unroll 4
    for (int k = kbase; k < kbase + 32; k++)
        s += w[k] * V[k * NDH + d];
    part[ks][d] = s;
    __syncthreads();
    if (threadIdx.x < 64)
        atomicAdd(&g_opos[bh * NDH + d], part[0][d] + part[1][d] + part[2][d] + part[3][d]);
}

// =====================================================================
// bf16 mma flash attention: K/V staged via cp.async (separate groups),
// P fragments packed in registers (no smem round-trip).
// smem: sKh/sKl/sVh/sVl 2048 u32 each + opos 64 floats = 33,024 B
// =====================================================================
#define ATTN_SMEM_BYTES (4 * 2048 * 4 + 64 * 4)

__global__ void __launch_bounds__(128, 2)
attn_mma(const float* __restrict__ gate) {
    extern __shared__ unsigned smu[];
    unsigned* sKh = smu;
    unsigned* sKl = smu + 2048;
    unsigned* sVh = smu + 4096;
    unsigned* sVl = smu + 6144;
    float* opos_s = (float*)(smu + 8192);

    int tid = threadIdx.x, lane = tid & 31, w = tid >> 5;
    int bh = blockIdx.y, q0 = blockIdx.x * 64;
    int h = bh & 7, b = bh >> 3;
    int g = lane >> 2, t = lane & 3;
    int mblk = (q0 >> 4) + w;
    int rowbase = w * 16;

    float gv = 1.0f / (1.0f + __expf(-gate[h]));
    float og = 1.0f - gv;
    if (tid < 64) opos_s[tid] = g_opos[bh * NDH + tid];

    const unsigned* kfh = g_kfh + (size_t)bh * 16384;
    const unsigned* kfl = g_kfl + (size_t)bh * 16384;
    const unsigned* vfh = g_vfh + (size_t)bh * 16384;
    const unsigned* vfl = g_vfl + (size_t)bh * 16384;

    auto stage_K = [&](int kc) {
        #pragma unroll
        for (int r = 0; r < 4; r++) {
            int i = (r * 128 + tid) * 4;          // 0..2047
            int kb = i >> 9, rem = i & 511;
            size_t off = ((size_t)(kb * 64 + kc * 8)) * 64 + rem;
            CPA16(cvta_sh(&sKh[i]), kfh + off);
            CPA16(cvta_sh(&sKl[i]), kfl + off);
        }
        asm volatile("cp.async.commit_group;");
    };
    auto stage_V = [&](int kc) {
        #pragma unroll
        for (int r = 0; r < 4; r++) {
            int i = (r * 128 + tid) * 4;
            size_t off = (size_t)kc * 2048 + i;   // contiguous per chunk
            CPA16(cvta_sh(&sVh[i]), vfh + off);
            CPA16(cvta_sh(&sVl[i]), vfl + off);
        }
        asm volatile("cp.async.commit_group;");
    };

    // Q fragments hoisted: 4 kblk16 x 4 regs (h + l)
    unsigned aqh[4][4], aql[4][4];
    {
        const unsigned* qh = g_qfh + (size_t)bh * 16384 + (size_t)mblk * 512;
        const unsigned* ql = g_qfl + (size_t)bh * 16384 + (size_t)mblk * 512;
        #pragma unroll
        for (int kb = 0; kb < 4; kb++) {
            uint4 hv = *(const uint4*)&qh[kb * 128 + lane * 4];
            uint4 lv = *(const uint4*)&ql[kb * 128 + lane * 4];
            aqh[kb][0] = hv.x; aqh[kb][1] = hv.y; aqh[kb][2] = hv.z; aqh[kb][3] = hv.w;
            aql[kb][0] = lv.x; aql[kb][1] = lv.y; aql[kb][2] = lv.z; aql[kb][3] = lv.w;
        }
    }

    stage_K(0);
    stage_V(0);

    float o[8][4] = {};
    float mrow[2] = {-1e30f, -1e30f};
    float lrow[2] = {0.0f, 0.0f};

    for (int kc = 0; kc < 8; kc++) {
        asm volatile("cp.async.wait_group 1;");   // K(kc) ready
        __syncthreads();

        // ---- S chunk = Q K^T (64q x 64kpos), bf16 3-split ----
        float sacc[8][4] = {};
        #pragma unroll
        for (int kb = 0; kb < 4; kb++) {
            #pragma unroll
            for (int nb = 0; nb < 8; nb++) {
                int off = kb * 512 + nb * 64 + lane * 2;
                uint2 bh2 = *(uint2*)&sKh[off];
                uint2 bl2 = *(uint2*)&sKl[off];
                mma_bf16(sacc[nb], aqh[kb], bh2.x, bh2.y);
                mma_bf16(sacc[nb], aqh[kb], bl2.x, bl2.y);
                mma_bf16(sacc[nb], aql[kb], bh2.x, bh2.y);
            }
        }
        __syncthreads();                  // all warps done reading K
        if (kc < 7) stage_K(kc + 1);      // overlap with softmax + PV

        // ---- online softmax ----
        #pragma unroll
        for (int j = 0; j < 2; j++) {
            float mx = -1e30f;
            #pragma unroll
            for (int nb = 0; nb < 8; nb++)
                mx = fmaxf(mx, fmaxf(sacc[nb][2*j], sacc[nb][2*j+1]));
            mx *= 0.125f;
            mx = fmaxf(mx, __shfl_xor_sync(0xFFFFFFFF, mx, 1));
            mx = fmaxf(mx, __shfl_xor_sync(0xFFFFFFFF, mx, 2));
            float mn = fmaxf(mrow[j], mx);
            float alpha = __expf(mrow[j] - mn);
            float rs = 0.0f;
            #pragma unroll
            for (int nb = 0; nb < 8; nb++) {
                float p0 = __expf(sacc[nb][2*j] * 0.125f - mn);
                float p1 = __expf(sacc[nb][2*j+1] * 0.125f - mn);
                sacc[nb][2*j] = p0; sacc[nb][2*j+1] = p1;
                rs += p0 + p1;
            }
            rs += __shfl_xor_sync(0xFFFFFFFF, rs, 1);
            rs += __shfl_xor_sync(0xFFFFFFFF, rs, 2);
            lrow[j] = lrow[j] * alpha + rs;
            mrow[j] = mn;
            #pragma unroll
            for (int nb = 0; nb < 8; nb++) { o[nb][2*j] *= alpha; o[nb][2*j+1] *= alpha; }
        }

        asm volatile("cp.async.wait_group 1;");   // V(kc) ready (K(kc+1) still in flight)
        __syncthreads();

        // ---- O += P @ V : P fragments packed directly from registers ----
        // A-frag for kblk16 kb: r0={P[g][16kb+2t],+1}=sacc[2kb][0,1]
        //   r1=row g+8: sacc[2kb][2,3]; r2={P[g][16kb+8+2t],+1}=sacc[2kb+1][0,1]
        //   r3=sacc[2kb+1][2,3]
        #pragma unroll
        for (int kb = 0; kb < 4; kb++) {
            unsigned ph[4], pl[4];
            #pragma unroll
            for (int r = 0; r < 4; r++) {
                int nbp = 2 * kb + (r >> 1);
                int e = (r & 1) * 2;
                float e0 = sacc[nbp][e], e1 = sacc[nbp][e + 1];
                float h0 = bf16f(e0), h1 = bf16f(e1);
                ph[r] = pk2(h0, h1);
                pl[r] = pk2(e0 - h0, e1 - h1);
            }
            #pragma unroll
            for (int nb = 0; nb < 8; nb++) {
                int off = kb * 512 + nb * 64 + lane * 2;
                uint2 vh2 = *(uint2*)&sVh[off];
                uint2 vl2 = *(uint2*)&sVl[off];
                mma_bf16(o[nb], ph, vh2.x, vh2.y);
                mma_bf16(o[nb], ph, vl2.x, vl2.y);
                mma_bf16(o[nb], pl, vh2.x, vh2.y);
            }
        }
        __syncthreads();                  // all warps done reading V
        if (kc < 7) stage_V(kc + 1);      // overlap with next QK
    }

    // ---- epilogue: out = og * o / l + gv * O_pos ----
    #pragma unroll
    for (int j = 0; j < 2; j++) {
        int q = q0 + rowbase + g + j * 8;
        float f = og / lrow[j];
        #pragma unroll
        for (int nb = 0; nb < 8; nb++) {
            int d = nb * 8 + 2 * t;
            *(float2*)&g_y[((size_t)b * NS + q) * NDIM + h * NDH + d] =
                make_float2(o[nb][2*j] * f + gv * opos_s[d],
                            o[nb][2*j+1] * f + gv * opos_s[d + 1]);
        }
    }
}

extern "C" void kernel_launch(void* const* d_in, const int* in_sizes, int n_in,
                              void* d_out, int out_size) {
    const float* x    = (const float*)d_in[0];
    const float* pos  = (const float*)d_in[1];
    const float* Wq   = (const float*)d_in[2];
    const float* Wk   = (const float*)d_in[3];
    const float* Wv   = (const float*)d_in[4];
    const float* Wo   = (const float*)d_in[5];
    const float* bo   = (const float*)d_in[6];
    const float* Wp1  = (const float*)d_in[7];
    const float* bp1  = (const float*)d_in[8];
    const float* Wp2  = (const float*)d_in[9];
    const float* bp2  = (const float*)d_in[10];
    const float* Wh   = (const float*)d_in[11];
    // d_in[12] = bh : cancels inside softmax — unused
    const float* gate = (const float*)d_in[13];
    float* out = (float*)d_out;

    static bool attr_set = false;
    if (!attr_set) {
        cudaFuncSetAttribute(attn_mma, cudaFuncAttributeMaxDynamicSharedMemorySize, ATTN_SMEM_BYTES);
        cudaFuncSetAttribute(qkv_mma, cudaFuncAttributeMaxDynamicSharedMemorySize, GEMM_SMEM_BYTES);
        cudaFuncSetAttribute(out_mma, cudaFuncAttributeMaxDynamicSharedMemorySize, GEMM_SMEM_BYTES);
        attr_set = true;
    }

    u_kernel<<<8, 256>>>(pos, Wp1, bp1, Wp2, bp2, Wh);
    pos_w_kernel<<<32, 512>>>();
    split_w_kernel<<<1024, 256>>>(Wq, Wk, Wv, Wo);
    split_x_kernel<<<512, 256>>>(x);
    qkv_mma<<<dim3(4, 16, 3), 256, GEMM_SMEM_BYTES>>>();
    split_q_kernel<<<512, 256>>>();
    split_kv_kernel<<<dim3(1024, 2), 256>>>();
    opos_kernel<<<dim3(32, 4), 256>>>();
    attn_mma<<<dim3(8, 32), 128, ATTN_SMEM_BYTES>>>(gate);
    split_y_kernel<<<512, 256>>>();
    out_mma<<<dim3(4, 16), 256, GEMM_SMEM_BYTES>>>(bo, out);
}

// round 14
// speedup vs baseline: 1.8750x; 1.0588x over previous
#include <cuda_runtime.h>
#include <cuda_bf16.h>
#include <math.h>

#define NB 4
#define NS 512
#define NDIM 512
#define NH 8
#define NDH 64
#define NM (NB*NS)     // 2048

// ---------------- device scratch (no allocations allowed) ----------------
__device__ float g_v[NB*NH*NS*NDH];     // [b][h][s][d] (needed by opos + split_v)
__device__ float g_u[NB*NS*NH];
__device__ float g_w[NB*NH*NS];
__device__ float g_opos[NB*NH*NDH];     // [b][h][d] : w @ V

// bf16 hi/lo packed fragment arrays (u32 = bf16x2, low half = even-k elem)
// Dense A-side (X or y): [mblk(128)][kblk(32)][lane(32)][reg(4)] = 524288 u32
__device__ unsigned g_xh[NM*NDIM/2], g_xl[NM*NDIM/2];
__device__ unsigned g_yh[NM*NDIM/2], g_yl[NM*NDIM/2];
// Dense B-side (W): per mat [kblk(32)][nblk(64)][lane(32)][reg(2)] = 131072 u32/mat
__device__ unsigned g_wh[4*NDIM*NDIM/2], g_wl[4*NDIM*NDIM/2];
#define WMAT_STRIDE (NDIM*NDIM/2)       // 131072
// Q A-side: [bh(32)][mblk(32)][kblk(4)][lane(32)][reg(4)] = 16384 u32/bh
__device__ unsigned g_qfh[NB*NH*NS*NDH/2], g_qfl[NB*NH*NS*NDH/2];
// K B-side: [bh][kblk(4 dim16)][nblk(64 pos8)][lane][reg(2)] = 16384 u32/bh
__device__ unsigned g_kfh[NB*NH*NS*NDH/2], g_kfl[NB*NH*NS*NDH/2];
// V B-side: [bh][kposblk(32)][nblk(8 dh8)][lane][reg(2)] = 16384 u32/bh
__device__ unsigned g_vfh[NB*NH*NS*NDH/2], g_vfl[NB*NH*NS*NDH/2];

__device__ __forceinline__ float bf16f(float x) {
    return __bfloat162float(__float2bfloat16_rn(x));
}
__device__ __forceinline__ unsigned pk2(float e0, float e1) {
    unsigned r;
    asm("cvt.rn.bf16x2.f32 %0, %1, %2;" : "=r"(r) : "f"(e1), "f"(e0));
    return r;
}

__device__ __forceinline__ void mma_bf16(float (&d)[4], const unsigned (&a)[4],
                                         unsigned b0, unsigned b1) {
    asm volatile(
        "mma.sync.aligned.m16n8k16.row.col.f32.bf16.bf16.f32 "
        "{%0,%1,%2,%3}, {%4,%5,%6,%7}, {%8,%9}, {%0,%1,%2,%3};"
        : "+f"(d[0]), "+f"(d[1]), "+f"(d[2]), "+f"(d[3])
        : "r"(a[0]), "r"(a[1]), "r"(a[2]), "r"(a[3]), "r"(b0), "r"(b1));
}

__device__ __forceinline__ unsigned cvta_sh(const void* p) {
    return (unsigned)__cvta_generic_to_shared(p);
}
#define CPA16(dst, src) \
    asm volatile("cp.async.cg.shared.global [%0], [%1], 16;" :: "r"(dst), "l"(src))

// ---------------- split kernels (X, W, V only) ----------------
__global__ void split_x_kernel(const float* __restrict__ X) {
    int gw = blockIdx.x * 8 + (threadIdx.x >> 5);   // 0..4095
    int lane = threadIdx.x & 31;
    int mblk = gw >> 5, kblk = gw & 31;
    int g = lane >> 2, t = lane & 3;
    unsigned hr[4], lr[4];
    #pragma unroll
    for (int r = 0; r < 4; r++) {
        int row = mblk * 16 + g + (r & 1) * 8;
        int col = kblk * 16 + 2 * t + (r >> 1) * 8;
        float2 v = *(const float2*)&X[row * NDIM + col];
        float h0 = bf16f(v.x), h1 = bf16f(v.y);
        hr[r] = pk2(h0, h1);
        lr[r] = pk2(v.x - h0, v.y - h1);
    }
    size_t idx = ((size_t)gw * 32 + lane) * 4;
    *(uint4*)&g_xh[idx] = make_uint4(hr[0], hr[1], hr[2], hr[3]);
    *(uint4*)&g_xl[idx] = make_uint4(lr[0], lr[1], lr[2], lr[3]);
}

__global__ void split_w_kernel(const float* __restrict__ Wq, const float* __restrict__ Wk,
                               const float* __restrict__ Wv, const float* __restrict__ Wo) {
    int gw = blockIdx.x * 8 + (threadIdx.x >> 5);   // 0..8191
    int lane = threadIdx.x & 31;
    int mat = gw >> 11, rem = gw & 2047;
    const float* W = (mat == 0) ? Wq : (mat == 1) ? Wk : (mat == 2) ? Wv : Wo;
    int kblk = rem >> 6, nblk = rem & 63;
    int g = lane >> 2, t = lane & 3;
    unsigned hr[2], lr[2];
    #pragma unroll
    for (int r = 0; r < 2; r++) {
        int k = kblk * 16 + 2 * t + r * 8;
        int n = nblk * 8 + g;
        float v0 = W[k * NDIM + n], v1 = W[(k + 1) * NDIM + n];
        float h0 = bf16f(v0), h1 = bf16f(v1);
        hr[r] = pk2(h0, h1);
        lr[r] = pk2(v0 - h0, v1 - h1);
    }
    size_t idx = (size_t)mat * WMAT_STRIDE + ((size_t)rem * 32 + lane) * 2;
    *(uint2*)&g_wh[idx] = make_uint2(hr[0], hr[1]);
    *(uint2*)&g_wl[idx] = make_uint2(lr[0], lr[1]);
}

// V B-side split (transpose across lanes -> must read from g_v floats)
__global__ void split_v_kernel() {
    int gw = blockIdx.x * 8 + (threadIdx.x >> 5);   // 0..8191
    int lane = threadIdx.x & 31;
    int g = lane >> 2, t = lane & 3;
    int bh = gw >> 8, rem = gw & 255;
    int kpb = rem >> 3, nblk = rem & 7;
    const float* V = g_v + (size_t)bh * NS * NDH;
    unsigned hr[2], lr[2];
    #pragma unroll
    for (int r = 0; r < 2; r++) {
        int k = kpb * 16 + 2 * t + r * 8;     // kpos
        int n = nblk * 8 + g;                 // dh
        float v0 = V[k * NDH + n], v1 = V[(k + 1) * NDH + n];
        float h0 = bf16f(v0), h1 = bf16f(v1);
        hr[r] = pk2(h0, h1);
        lr[r] = pk2(v0 - h0, v1 - h1);
    }
    size_t idx = ((size_t)gw * 32 + lane) * 2;   // [bh][kpb][nblk][lane][2]
    *(uint2*)&g_vfh[idx] = make_uint2(hr[0], hr[1]);
    *(uint2*)&g_vfl[idx] = make_uint2(lr[0], lr[1]);
}

// =====================================================================
// bf16 x3 MMA GEMM core, 128x128 tile, 8 warps, k16 stages, 3 buffers.
// =====================================================================
#define GEMM_SMEM_BYTES (3 * 4096 * 4)   // 49152

__device__ __forceinline__ void mma_gemm_bf16(const unsigned* __restrict__ Ah,
                                              const unsigned* __restrict__ Al,
                                              const unsigned* __restrict__ Bh,
                                              const unsigned* __restrict__ Bl,
                                              int mblk0, int nblk0,
                                              float (&acc)[2][8][4], unsigned* sm) {
    int tid = threadIdx.x, lane = tid & 31, wid = tid >> 5;
    int warp_m = wid >> 1, warp_n = wid & 1;
    int a_mb = tid >> 5, a_ln = tid & 31;
    int b_nb = tid >> 4, b_j = tid & 15;

    const unsigned* srcAh = Ah + (size_t)(mblk0 + a_mb) * 4096 + a_ln * 4;
    const unsigned* srcAl = Al + (size_t)(mblk0 + a_mb) * 4096 + a_ln * 4;
    const unsigned* srcBh = Bh + (size_t)(nblk0 + b_nb) * 64 + b_j * 4;
    const unsigned* srcBl = Bl + (size_t)(nblk0 + b_nb) * 64 + b_j * 4;

    auto issue = [&](int s) {
        unsigned* base = sm + (s % 3) * 4096;
        CPA16(cvta_sh(base + a_mb * 128 + a_ln * 4),        srcAh + s * 128);
        CPA16(cvta_sh(base + 1024 + a_mb * 128 + a_ln * 4), srcAl + s * 128);
        CPA16(cvta_sh(base + 2048 + b_nb * 64 + b_j * 4),   srcBh + (size_t)s * 4096);
        CPA16(cvta_sh(base + 3072 + b_nb * 64 + b_j * 4),   srcBl + (size_t)s * 4096);
        asm volatile("cp.async.commit_group;");
    };

    issue(0);
    issue(1);
    for (int s = 0; s < 32; s++) {
        if (s < 31) asm volatile("cp.async.wait_group 1;");
        else        asm volatile("cp.async.wait_group 0;");
        __syncthreads();
        if (s < 30) issue(s + 2);
        unsigned* base = sm + (s % 3) * 4096;
        unsigned ah[2][4], al[2][4];
        #pragma unroll
        for (int mb2 = 0; mb2 < 2; mb2++) {
            uint4 h4 = *(uint4*)(base + (warp_m * 2 + mb2) * 128 + lane * 4);
            uint4 l4 = *(uint4*)(base + 1024 + (warp_m * 2 + mb2) * 128 + lane * 4);
            ah[mb2][0] = h4.x; ah[mb2][1] = h4.y; ah[mb2][2] = h4.z; ah[mb2][3] = h4.w;
            al[mb2][0] = l4.x; al[mb2][1] = l4.y; al[mb2][2] = l4.z; al[mb2][3] = l4.w;
        }
        #pragma unroll
        for (int nb = 0; nb < 8; nb++) {
            uint2 bh2 = *(uint2*)(base + 2048 + (warp_n * 8 + nb) * 64 + lane * 2);
            uint2 bl2 = *(uint2*)(base + 3072 + (warp_n * 8 + nb) * 64 + lane * 2);
            #pragma unroll
            for (int mb2 = 0; mb2 < 2; mb2++) {
                mma_bf16(acc[mb2][nb], ah[mb2], bh2.x, bh2.y);
                mma_bf16(acc[mb2][nb], ah[mb2], bl2.x, bl2.y);
                mma_bf16(acc[mb2][nb], al[mb2], bh2.x, bh2.y);
            }
        }
    }
}

// ---------------- QKV projection: epilogue emits fragments directly -----
__global__ void __launch_bounds__(256, 2)
qkv_mma() {
    extern __shared__ unsigned gsm[];
    int mat = blockIdx.z;
    const unsigned* Bh = g_wh + (size_t)mat * WMAT_STRIDE;
    const unsigned* Bl = g_wl + (size_t)mat * WMAT_STRIDE;
    int m0 = blockIdx.y * 128, n0 = blockIdx.x * 128;
    float acc[2][8][4] = {};
    mma_gemm_bf16(g_xh, g_xl, Bh, Bl, m0 >> 4, n0 >> 3, acc, gsm);

    int lane = threadIdx.x & 31, wid = threadIdx.x >> 5;
    int warp_m = wid >> 1, warp_n = wid & 1;
    int g = lane >> 2, t = lane & 3;
    int hq = (n0 >> 6) + warp_n;          // head index 0..7
    #pragma unroll
    for (int mb2 = 0; mb2 < 2; mb2++) {
        int mbase = m0 + warp_m * 32 + mb2 * 16;   // multiple of 16
        int b = mbase >> 9, sbase = mbase & 511;
        int bh = b * NH + hq;
        if (mat == 0) {
            // Q A-fragments: reg r = j | ((nb&1)<<1), kblk = nb>>1
            size_t base = (size_t)bh * 16384 + (size_t)(sbase >> 4) * 512;
            #pragma unroll
            for (int kb = 0; kb < 4; kb++) {
                unsigned hr[4], lr[4];
                #pragma unroll
                for (int r = 0; r < 4; r++) {
                    int nb = 2 * kb + (r >> 1), e = (r & 1) * 2;
                    float e0 = acc[mb2][nb][e], e1 = acc[mb2][nb][e + 1];
                    float h0 = bf16f(e0), h1 = bf16f(e1);
                    hr[r] = pk2(h0, h1);
                    lr[r] = pk2(e0 - h0, e1 - h1);
                }
                *(uint4*)&g_qfh[base + kb * 128 + lane * 4] = make_uint4(hr[0], hr[1], hr[2], hr[3]);
                *(uint4*)&g_qfl[base + kb * 128 + lane * 4] = make_uint4(lr[0], lr[1], lr[2], lr[3]);
            }
        } else if (mat == 1) {
            // K B-fragments: reg = nb&1, kblk_dim = nb>>1, nblk_pos = sbase/8 + j
            int nblk0 = sbase >> 3;
            #pragma unroll
            for (int kb = 0; kb < 4; kb++)
                #pragma unroll
                for (int j = 0; j < 2; j++) {
                    unsigned h0r, h1r, l0r, l1r;
                    {
                        float e0 = acc[mb2][2*kb][2*j], e1 = acc[mb2][2*kb][2*j+1];
                        float a0 = bf16f(e0), a1 = bf16f(e1);
                        h0r = pk2(a0, a1); l0r = pk2(e0 - a0, e1 - a1);
                    }
                    {
                        float e0 = acc[mb2][2*kb+1][2*j], e1 = acc[mb2][2*kb+1][2*j+1];
                        float a0 = bf16f(e0), a1 = bf16f(e1);
                        h1r = pk2(a0, a1); l1r = pk2(e0 - a0, e1 - a1);
                    }
                    size_t idx = (size_t)bh * 16384 + (size_t)kb * 4096 + (size_t)(nblk0 + j) * 64 + lane * 2;
                    *(uint2*)&g_kfh[idx] = make_uint2(h0r, h1r);
                    *(uint2*)&g_kfl[idx] = make_uint2(l0r, l1r);
                }
        } else {
            // V: float stores (opos + split_v consume)
            #pragma unroll
            for (int nb = 0; nb < 8; nb++) {
                int d = nb * 8 + 2 * t;
                *(float2*)&g_v[((size_t)bh * NS + sbase + g) * NDH + d] =
                    make_float2(acc[mb2][nb][0], acc[mb2][nb][1]);
                *(float2*)&g_v[((size_t)bh * NS + sbase + g + 8) * NDH + d] =
                    make_float2(acc[mb2][nb][2], acc[mb2][nb][3]);
            }
        }
    }
}

// ---------------- out = y @ Wo + bo ----------------
__global__ void __launch_bounds__(256, 2)
out_mma(const float* __restrict__ bo, float* __restrict__ out) {
    extern __shared__ unsigned gsm[];
    const unsigned* Bh = g_wh + (size_t)3 * WMAT_STRIDE;
    const unsigned* Bl = g_wl + (size_t)3 * WMAT_STRIDE;
    int m0 = blockIdx.y * 128, n0 = blockIdx.x * 128;
    float acc[2][8][4] = {};
    mma_gemm_bf16(g_yh, g_yl, Bh, Bl, m0 >> 4, n0 >> 3, acc, gsm);

    int lane = threadIdx.x & 31, wid = threadIdx.x >> 5;
    int warp_m = wid >> 1, warp_n = wid & 1;
    int g = lane >> 2, t = lane & 3;
    #pragma unroll
    for (int mb2 = 0; mb2 < 2; mb2++) {
        int mrow = m0 + warp_m * 32 + mb2 * 16 + g;
        #pragma unroll
        for (int nb = 0; nb < 8; nb++) {
            int ncol = n0 + (warp_n * 8 + nb) * 8 + 2 * t;
            float b0 = bo[ncol], b1 = bo[ncol + 1];
            *(float2*)&out[(size_t)mrow * NDIM + ncol] =
                make_float2(acc[mb2][nb][0] + b0, acc[mb2][nb][1] + b1);
            *(float2*)&out[(size_t)(mrow + 8) * NDIM + ncol] =
                make_float2(acc[mb2][nb][2] + b0, acc[mb2][nb][3] + b1);
        }
    }
}

// ---------------- tiny positional MLP ----------------
__global__ void u_kernel(const float* __restrict__ pos,
                         const float* __restrict__ Wp1, const float* __restrict__ bp1,
                         const float* __restrict__ Wp2, const float* __restrict__ bp2,
                         const float* __restrict__ Wh) {
    int idx = blockIdx.x * blockDim.x + threadIdx.x;
    if (idx >= NM) return;
    g_opos[idx & (NB*NH*NDH - 1)] = 0.0f;
    const float* pp = pos + idx * 3;
    float p0 = pp[0], p1 = pp[1], p2 = pp[2];
    float h1[3];
    #pragma unroll
    for (int j = 0; j < 3; j++)
        h1[j] = fmaxf(0.0f, p0 * Wp1[j] + p1 * Wp1[3 + j] + p2 * Wp1[6 + j] + bp1[j]);
    float u[NH];
    #pragma unroll
    for (int hh = 0; hh < NH; hh++) u[hh] = 0.0f;
    for (int j = 0; j < 64; j++) {
        float pv = h1[0] * Wp2[j] + h1[1] * Wp2[64 + j] + h1[2] * Wp2[128 + j] + bp2[j];
        #pragma unroll
        for (int hh = 0; hh < NH; hh++) u[hh] += pv * Wh[j * NH + hh];
    }
    #pragma unroll
    for (int hh = 0; hh < NH; hh++) g_u[idx * NH + hh] = u[hh];
}

__global__ void pos_w_kernel() {
    __shared__ float red[512];
    int bh = blockIdx.x;
    int b = bh >> 3, h = bh & 7;
    int k = threadIdx.x;
    float t = -g_u[(b * NS + k) * NH + h];
    red[k] = t; __syncthreads();
    for (int s = 256; s > 0; s >>= 1) { if (k < s) red[k] = fmaxf(red[k], red[k + s]); __syncthreads(); }
    float m = red[0]; __syncthreads();
    float e = expf(t - m);
    red[k] = e; __syncthreads();
    for (int s = 256; s > 0; s >>= 1) { if (k < s) red[k] += red[k + s]; __syncthreads(); }
    g_w[bh * NS + k] = e / red[0];
}

__global__ void opos_kernel() {
    __shared__ float part[4][64];
    int bh = blockIdx.x;
    int kq = blockIdx.y;
    int d = threadIdx.x & 63;
    int ks = threadIdx.x >> 6;
    const float* V = g_v + (size_t)bh * NS * NDH;
    const float* w = g_w + bh * NS;
    int kbase = kq * 128 + ks * 32;
    float s = 0.0f;
    #pragma unroll 4
    for (int k = kbase; k < kbase + 32; k++)
        s += w[k] * V[k * NDH + d];
    part[ks][d] = s;
    __syncthreads();
    if (threadIdx.x < 64)
        atomicAdd(&g_opos[bh * NDH + d], part[0][d] + part[1][d] + part[2][d] + part[3][d]);
}

// =====================================================================
// bf16 mma flash attention: K/V staged via cp.async, P in registers,
// epilogue emits y A-fragments directly (no g_y float tensor).
// =====================================================================
#define ATTN_SMEM_BYTES (4 * 2048 * 4 + 64 * 4)

__global__ void __launch_bounds__(128, 2)
attn_mma(const float* __restrict__ gate) {
    extern __shared__ unsigned smu[];
    unsigned* sKh = smu;
    unsigned* sKl = smu + 2048;
    unsigned* sVh = smu + 4096;
    unsigned* sVl = smu + 6144;
    float* opos_s = (float*)(smu + 8192);

    int tid = threadIdx.x, lane = tid & 31, w = tid >> 5;
    int bh = blockIdx.y, q0 = blockIdx.x * 64;
    int h = bh & 7, b = bh >> 3;
    int g = lane >> 2, t = lane & 3;
    int mblk = (q0 >> 4) + w;
    int rowbase = w * 16;

    float gv = 1.0f / (1.0f + __expf(-gate[h]));
    float og = 1.0f - gv;
    if (tid < 64) opos_s[tid] = g_opos[bh * NDH + tid];

    const unsigned* kfh = g_kfh + (size_t)bh * 16384;
    const unsigned* kfl = g_kfl + (size_t)bh * 16384;
    const unsigned* vfh = g_vfh + (size_t)bh * 16384;
    const unsigned* vfl = g_vfl + (size_t)bh * 16384;

    auto stage_K = [&](int kc) {
        #pragma unroll
        for (int r = 0; r < 4; r++) {
            int i = (r * 128 + tid) * 4;          // 0..2047
            int kb = i >> 9, rem = i & 511;
            size_t off = ((size_t)(kb * 64 + kc * 8)) * 64 + rem;
            CPA16(cvta_sh(&sKh[i]), kfh + off);
            CPA16(cvta_sh(&sKl[i]), kfl + off);
        }
        asm volatile("cp.async.commit_group;");
    };
    auto stage_V = [&](int kc) {
        #pragma unroll
        for (int r = 0; r < 4; r++) {
            int i = (r * 128 + tid) * 4;
            size_t off = (size_t)kc * 2048 + i;
            CPA16(cvta_sh(&sVh[i]), vfh + off);
            CPA16(cvta_sh(&sVl[i]), vfl + off);
        }
        asm volatile("cp.async.commit_group;");
    };

    // Q fragments hoisted
    unsigned aqh[4][4], aql[4][4];
    {
        const unsigned* qh = g_qfh + (size_t)bh * 16384 + (size_t)mblk * 512;
        const unsigned* ql = g_qfl + (size_t)bh * 16384 + (size_t)mblk * 512;
        #pragma unroll
        for (int kb = 0; kb < 4; kb++) {
            uint4 hv = *(const uint4*)&qh[kb * 128 + lane * 4];
            uint4 lv = *(const uint4*)&ql[kb * 128 + lane * 4];
            aqh[kb][0] = hv.x; aqh[kb][1] = hv.y; aqh[kb][2] = hv.z; aqh[kb][3] = hv.w;
            aql[kb][0] = lv.x; aql[kb][1] = lv.y; aql[kb][2] = lv.z; aql[kb][3] = lv.w;
        }
    }

    stage_K(0);
    stage_V(0);

    float o[8][4] = {};
    float mrow[2] = {-1e30f, -1e30f};
    float lrow[2] = {0.0f, 0.0f};

    for (int kc = 0; kc < 8; kc++) {
        asm volatile("cp.async.wait_group 1;");   // K(kc) ready
        __syncthreads();

        float sacc[8][4] = {};
        #pragma unroll
        for (int kb = 0; kb < 4; kb++) {
            #pragma unroll
            for (int nb = 0; nb < 8; nb++) {
                int off = kb * 512 + nb * 64 + lane * 2;
                uint2 bh2 = *(uint2*)&sKh[off];
                uint2 bl2 = *(uint2*)&sKl[off];
                mma_bf16(sacc[nb], aqh[kb], bh2.x, bh2.y);
                mma_bf16(sacc[nb], aqh[kb], bl2.x, bl2.y);
                mma_bf16(sacc[nb], aql[kb], bh2.x, bh2.y);
            }
        }
        __syncthreads();
        if (kc < 7) stage_K(kc + 1);

        // online softmax
        #pragma unroll
        for (int j = 0; j < 2; j++) {
            float mx = -1e30f;
            #pragma unroll
            for (int nb = 0; nb < 8; nb++)
                mx = fmaxf(mx, fmaxf(sacc[nb][2*j], sacc[nb][2*j+1]));
            mx *= 0.125f;
            mx = fmaxf(mx, __shfl_xor_sync(0xFFFFFFFF, mx, 1));
            mx = fmaxf(mx, __shfl_xor_sync(0xFFFFFFFF, mx, 2));
            float mn = fmaxf(mrow[j], mx);
            float alpha = __expf(mrow[j] - mn);
            float rs = 0.0f;
            #pragma unroll
            for (int nb = 0; nb < 8; nb++) {
                float p0 = __expf(sacc[nb][2*j] * 0.125f - mn);
                float p1 = __expf(sacc[nb][2*j+1] * 0.125f - mn);
                sacc[nb][2*j] = p0; sacc[nb][2*j+1] = p1;
                rs += p0 + p1;
            }
            rs += __shfl_xor_sync(0xFFFFFFFF, rs, 1);
            rs += __shfl_xor_sync(0xFFFFFFFF, rs, 2);
            lrow[j] = lrow[j] * alpha + rs;
            mrow[j] = mn;
            #pragma unroll
            for (int nb = 0; nb < 8; nb++) { o[nb][2*j] *= alpha; o[nb][2*j+1] *= alpha; }
        }

        asm volatile("cp.async.wait_group 1;");   // V(kc) ready
        __syncthreads();

        // O += P @ V, P fragments packed from registers
        #pragma unroll
        for (int kb = 0; kb < 4; kb++) {
            unsigned ph[4], pl[4];
            #pragma unroll
            for (int r = 0; r < 4; r++) {
                int nbp = 2 * kb + (r >> 1);
                int e = (r & 1) * 2;
                float e0 = sacc[nbp][e], e1 = sacc[nbp][e + 1];
                float h0 = bf16f(e0), h1 = bf16f(e1);
                ph[r] = pk2(h0, h1);
                pl[r] = pk2(e0 - h0, e1 - h1);
            }
            #pragma unroll
            for (int nb = 0; nb < 8; nb++) {
                int off = kb * 512 + nb * 64 + lane * 2;
                uint2 vh2 = *(uint2*)&sVh[off];
                uint2 vl2 = *(uint2*)&sVl[off];
                mma_bf16(o[nb], ph, vh2.x, vh2.y);
                mma_bf16(o[nb], ph, vl2.x, vl2.y);
                mma_bf16(o[nb], pl, vh2.x, vh2.y);
            }
        }
        __syncthreads();
        if (kc < 7) stage_V(kc + 1);
    }

    // ---- epilogue: emit y A-fragments directly ----
    // y row = b*512 + q0 + rowbase + g + 8j; col = h*64 + nb*8 + 2t
    // A-frag reg r = j | ((nb&1)<<1); kblk = h*4 + (nb>>1)
    {
        int mblk_y = (b * NS + q0 + rowbase) >> 4;     // 0..127
        size_t ybase = (size_t)mblk_y * 4096 + (size_t)h * 512;
        float f0 = og / lrow[0], f1 = og / lrow[1];
        #pragma unroll
        for (int kb = 0; kb < 4; kb++) {
            unsigned hr[4], lr[4];
            #pragma unroll
            for (int r = 0; r < 4; r++) {
                int nb = 2 * kb + (r >> 1);
                int j = r & 1;
                float f = j ? f1 : f0;
                int d0 = nb * 8 + 2 * t;
                float e0 = o[nb][2*j]   * f + gv * opos_s[d0];
                float e1 = o[nb][2*j+1] * f + gv * opos_s[d0 + 1];
                float h0 = bf16f(e0), h1 = bf16f(e1);
                hr[r] = pk2(h0, h1);
                lr[r] = pk2(e0 - h0, e1 - h1);
            }
            *(uint4*)&g_yh[ybase + kb * 128 + lane * 4] = make_uint4(hr[0], hr[1], hr[2], hr[3]);
            *(uint4*)&g_yl[ybase + kb * 128 + lane * 4] = make_uint4(lr[0], lr[1], lr[2], lr[3]);
        }
    }
}

extern "C" void kernel_launch(void* const* d_in, const int* in_sizes, int n_in,
                              void* d_out, int out_size) {
    const float* x    = (const float*)d_in[0];
    const float* pos  = (const float*)d_in[1];
    const float* Wq   = (const float*)d_in[2];
    const float* Wk   = (const float*)d_in[3];
    const float* Wv   = (const float*)d_in[4];
    const float* Wo   = (const float*)d_in[5];
    const float* bo   = (const float*)d_in[6];
    const float* Wp1  = (const float*)d_in[7];
    const float* bp1  = (const float*)d_in[8];
    const float* Wp2  = (const float*)d_in[9];
    const float* bp2  = (const float*)d_in[10];
    const float* Wh   = (const float*)d_in[11];
    // d_in[12] = bh : cancels inside softmax — unused
    const float* gate = (const float*)d_in[13];
    float* out = (float*)d_out;

    static bool attr_set = false;
    if (!attr_set) {
        cudaFuncSetAttribute(attn_mma, cudaFuncAttributeMaxDynamicSharedMemorySize, ATTN_SMEM_BYTES);
        cudaFuncSetAttribute(qkv_mma, cudaFuncAttributeMaxDynamicSharedMemorySize, GEMM_SMEM_BYTES);
        cudaFuncSetAttribute(out_mma, cudaFuncAttributeMaxDynamicSharedMemorySize, GEMM_SMEM_BYTES);
        attr_set = true;
    }

    u_kernel<<<8, 256>>>(pos, Wp1, bp1, Wp2, bp2, Wh);
    pos_w_kernel<<<32, 512>>>();
    split_w_kernel<<<1024, 256>>>(Wq, Wk, Wv, Wo);
    split_x_kernel<<<512, 256>>>(x);
    qkv_mma<<<dim3(4, 16, 3), 256, GEMM_SMEM_BYTES>>>();
    split_v_kernel<<<1024, 256>>>();
    opos_kernel<<<dim3(32, 4), 256>>>();
    attn_mma<<<dim3(8, 32), 128, ATTN_SMEM_BYTES>>>(gate);
    out_mma<<<dim3(4, 16), 256, GEMM_SMEM_BYTES>>>(bo, out);
}

// round 15
// speedup vs baseline: 2.0593x; 1.0983x over previous
#include <cuda_runtime.h>
#include <cuda_bf16.h>
#include <math.h>

#define NB 4
#define NS 512
#define NDIM 512
#define NH 8
#define NDH 64
#define NM (NB*NS)     // 2048

// ---------------- device scratch (no allocations allowed) ----------------
__device__ float g_v[NB*NH*NS*NDH];     // [b][h][s][d] (opos + split_v consume)
__device__ float g_w[NB*NH*NS];
__device__ float g_opos[NB*NH*NDH];     // [b][h][d] : w @ V

// bf16 hi/lo packed fragment arrays (u32 = bf16x2, low half = even-k elem)
__device__ unsigned g_xh[NM*NDIM/2], g_xl[NM*NDIM/2];
__device__ unsigned g_yh[NM*NDIM/2], g_yl[NM*NDIM/2];
__device__ unsigned g_wh[4*NDIM*NDIM/2], g_wl[4*NDIM*NDIM/2];
#define WMAT_STRIDE (NDIM*NDIM/2)       // 131072
__device__ unsigned g_qfh[NB*NH*NS*NDH/2], g_qfl[NB*NH*NS*NDH/2];
__device__ unsigned g_kfh[NB*NH*NS*NDH/2], g_kfl[NB*NH*NS*NDH/2];
__device__ unsigned g_vfh[NB*NH*NS*NDH/2], g_vfl[NB*NH*NS*NDH/2];

__device__ __forceinline__ float bf16f(float x) {
    return __bfloat162float(__float2bfloat16_rn(x));
}
__device__ __forceinline__ unsigned pk2(float e0, float e1) {
    unsigned r;
    asm("cvt.rn.bf16x2.f32 %0, %1, %2;" : "=r"(r) : "f"(e1), "f"(e0));
    return r;
}

__device__ __forceinline__ void mma_bf16(float (&d)[4], const unsigned (&a)[4],
                                         unsigned b0, unsigned b1) {
    asm volatile(
        "mma.sync.aligned.m16n8k16.row.col.f32.bf16.bf16.f32 "
        "{%0,%1,%2,%3}, {%4,%5,%6,%7}, {%8,%9}, {%0,%1,%2,%3};"
        : "+f"(d[0]), "+f"(d[1]), "+f"(d[2]), "+f"(d[3])
        : "r"(a[0]), "r"(a[1]), "r"(a[2]), "r"(a[3]), "r"(b0), "r"(b1));
}

__device__ __forceinline__ unsigned cvta_sh(const void* p) {
    return (unsigned)__cvta_generic_to_shared(p);
}
#define CPA16(dst, src) \
    asm volatile("cp.async.cg.shared.global [%0], [%1], 16;" :: "r"(dst), "l"(src))

// ---------------- fused prep: split_w (blocks 0..1023) + split_x (1024..1535)
__global__ void prep_kernel(const float* __restrict__ X,
                            const float* __restrict__ Wq, const float* __restrict__ Wk,
                            const float* __restrict__ Wv, const float* __restrict__ Wo) {
    int lane = threadIdx.x & 31;
    int g = lane >> 2, t = lane & 3;
    if (blockIdx.x < 1024) {
        // ---- split_w ----
        int gw = blockIdx.x * 8 + (threadIdx.x >> 5);   // 0..8191
        int mat = gw >> 11, rem = gw & 2047;
        const float* W = (mat == 0) ? Wq : (mat == 1) ? Wk : (mat == 2) ? Wv : Wo;
        int kblk = rem >> 6, nblk = rem & 63;
        unsigned hr[2], lr[2];
        #pragma unroll
        for (int r = 0; r < 2; r++) {
            int k = kblk * 16 + 2 * t + r * 8;
            int n = nblk * 8 + g;
            float v0 = W[k * NDIM + n], v1 = W[(k + 1) * NDIM + n];
            float h0 = bf16f(v0), h1 = bf16f(v1);
            hr[r] = pk2(h0, h1);
            lr[r] = pk2(v0 - h0, v1 - h1);
        }
        size_t idx = (size_t)mat * WMAT_STRIDE + ((size_t)rem * 32 + lane) * 2;
        *(uint2*)&g_wh[idx] = make_uint2(hr[0], hr[1]);
        *(uint2*)&g_wl[idx] = make_uint2(lr[0], lr[1]);
    } else {
        // ---- split_x ----
        int gw = (blockIdx.x - 1024) * 8 + (threadIdx.x >> 5);  // 0..4095
        int mblk = gw >> 5, kblk = gw & 31;
        unsigned hr[4], lr[4];
        #pragma unroll
        for (int r = 0; r < 4; r++) {
            int row = mblk * 16 + g + (r & 1) * 8;
            int col = kblk * 16 + 2 * t + (r >> 1) * 8;
            float2 v = *(const float2*)&X[row * NDIM + col];
            float h0 = bf16f(v.x), h1 = bf16f(v.y);
            hr[r] = pk2(h0, h1);
            lr[r] = pk2(v.x - h0, v.y - h1);
        }
        size_t idx = ((size_t)gw * 32 + lane) * 4;
        *(uint4*)&g_xh[idx] = make_uint4(hr[0], hr[1], hr[2], hr[3]);
        *(uint4*)&g_xl[idx] = make_uint4(lr[0], lr[1], lr[2], lr[3]);
    }
}

// ---------------- fused positional path: MLP + softmax row w; zero opos ---
__global__ void pos_w_kernel(const float* __restrict__ pos,
                             const float* __restrict__ Wp1, const float* __restrict__ bp1,
                             const float* __restrict__ Wp2, const float* __restrict__ bp2,
                             const float* __restrict__ Wh) {
    __shared__ float red[512];
    int bh = blockIdx.x;
    int b = bh >> 3, h = bh & 7;
    int k = threadIdx.x;
    if (k < 64) g_opos[bh * NDH + k] = 0.0f;
    // inline MLP: u = (relu(pos@Wp1+bp1)@Wp2+bp2)@Wh[:,h]
    const float* pp = pos + ((size_t)b * NS + k) * 3;
    float p0 = pp[0], p1 = pp[1], p2 = pp[2];
    float h1[3];
    #pragma unroll
    for (int j = 0; j < 3; j++)
        h1[j] = fmaxf(0.0f, p0 * Wp1[j] + p1 * Wp1[3 + j] + p2 * Wp1[6 + j] + bp1[j]);
    float u = 0.0f;
    for (int j = 0; j < 64; j++) {
        float pv = h1[0] * Wp2[j] + h1[1] * Wp2[64 + j] + h1[2] * Wp2[128 + j] + bp2[j];
        u += pv * Wh[j * NH + h];
    }
    float t = -u;
    red[k] = t; __syncthreads();
    for (int s = 256; s > 0; s >>= 1) { if (k < s) red[k] = fmaxf(red[k], red[k + s]); __syncthreads(); }
    float m = red[0]; __syncthreads();
    float e = expf(t - m);
    red[k] = e; __syncthreads();
    for (int s = 256; s > 0; s >>= 1) { if (k < s) red[k] += red[k + s]; __syncthreads(); }
    g_w[bh * NS + k] = e / red[0];
}

// ---------------- fused: split_v (blocks 0..1023) + opos (1024..1151) ----
__global__ void vprep_kernel() {
    if (blockIdx.x < 1024) {
        // ---- split_v ----
        int gw = blockIdx.x * 8 + (threadIdx.x >> 5);   // 0..8191
        int lane = threadIdx.x & 31;
        int g = lane >> 2, t = lane & 3;
        int bh = gw >> 8, rem = gw & 255;
        int kpb = rem >> 3, nblk = rem & 7;
        const float* V = g_v + (size_t)bh * NS * NDH;
        unsigned hr[2], lr[2];
        #pragma unroll
        for (int r = 0; r < 2; r++) {
            int k = kpb * 16 + 2 * t + r * 8;     // kpos
            int n = nblk * 8 + g;                 // dh
            float v0 = V[k * NDH + n], v1 = V[(k + 1) * NDH + n];
            float h0 = bf16f(v0), h1 = bf16f(v1);
            hr[r] = pk2(h0, h1);
            lr[r] = pk2(v0 - h0, v1 - h1);
        }
        size_t idx = ((size_t)gw * 32 + lane) * 2;
        *(uint2*)&g_vfh[idx] = make_uint2(hr[0], hr[1]);
        *(uint2*)&g_vfl[idx] = make_uint2(lr[0], lr[1]);
    } else {
        // ---- opos partial ----
        __shared__ float part[4][64];
        int idx = blockIdx.x - 1024;         // 0..127
        int bh = idx >> 2, kq = idx & 3;
        int d = threadIdx.x & 63;
        int ks = threadIdx.x >> 6;
        const float* V = g_v + (size_t)bh * NS * NDH;
        const float* w = g_w + bh * NS;
        int kbase = kq * 128 + ks * 32;
        float s = 0.0f;
        #pragma unroll 4
        for (int k = kbase; k < kbase + 32; k++)
            s += w[k] * V[k * NDH + d];
        part[ks][d] = s;
        __syncthreads();
        if (threadIdx.x < 64)
            atomicAdd(&g_opos[bh * NDH + d], part[0][d] + part[1][d] + part[2][d] + part[3][d]);
    }
}

// =====================================================================
// bf16 x3 MMA GEMM core, 128x128 tile, 8 warps, k16 stages, 3 buffers.
// =====================================================================
#define GEMM_SMEM_BYTES (3 * 4096 * 4)   // 49152

__device__ __forceinline__ void mma_gemm_bf16(const unsigned* __restrict__ Ah,
                                              const unsigned* __restrict__ Al,
                                              const unsigned* __restrict__ Bh,
                                              const unsigned* __restrict__ Bl,
                                              int mblk0, int nblk0,
                                              float (&acc)[2][8][4], unsigned* sm) {
    int tid = threadIdx.x, lane = tid & 31, wid = tid >> 5;
    int warp_m = wid >> 1, warp_n = wid & 1;
    int a_mb = tid >> 5, a_ln = tid & 31;
    int b_nb = tid >> 4, b_j = tid & 15;

    const unsigned* srcAh = Ah + (size_t)(mblk0 + a_mb) * 4096 + a_ln * 4;
    const unsigned* srcAl = Al + (size_t)(mblk0 + a_mb) * 4096 + a_ln * 4;
    const unsigned* srcBh = Bh + (size_t)(nblk0 + b_nb) * 64 + b_j * 4;
    const unsigned* srcBl = Bl + (size_t)(nblk0 + b_nb) * 64 + b_j * 4;

    auto issue = [&](int s) {
        unsigned* base = sm + (s % 3) * 4096;
        CPA16(cvta_sh(base + a_mb * 128 + a_ln * 4),        srcAh + s * 128);
        CPA16(cvta_sh(base + 1024 + a_mb * 128 + a_ln * 4), srcAl + s * 128);
        CPA16(cvta_sh(base + 2048 + b_nb * 64 + b_j * 4),   srcBh + (size_t)s * 4096);
        CPA16(cvta_sh(base + 3072 + b_nb * 64 + b_j * 4),   srcBl + (size_t)s * 4096);
        asm volatile("cp.async.commit_group;");
    };

    issue(0);
    issue(1);
    for (int s = 0; s < 32; s++) {
        if (s < 31) asm volatile("cp.async.wait_group 1;");
        else        asm volatile("cp.async.wait_group 0;");
        __syncthreads();
        if (s < 30) issue(s + 2);
        unsigned* base = sm + (s % 3) * 4096;
        unsigned ah[2][4], al[2][4];
        #pragma unroll
        for (int mb2 = 0; mb2 < 2; mb2++) {
            uint4 h4 = *(uint4*)(base + (warp_m * 2 + mb2) * 128 + lane * 4);
            uint4 l4 = *(uint4*)(base + 1024 + (warp_m * 2 + mb2) * 128 + lane * 4);
            ah[mb2][0] = h4.x; ah[mb2][1] = h4.y; ah[mb2][2] = h4.z; ah[mb2][3] = h4.w;
            al[mb2][0] = l4.x; al[mb2][1] = l4.y; al[mb2][2] = l4.z; al[mb2][3] = l4.w;
        }
        #pragma unroll
        for (int nb = 0; nb < 8; nb++) {
            uint2 bh2 = *(uint2*)(base + 2048 + (warp_n * 8 + nb) * 64 + lane * 2);
            uint2 bl2 = *(uint2*)(base + 3072 + (warp_n * 8 + nb) * 64 + lane * 2);
            #pragma unroll
            for (int mb2 = 0; mb2 < 2; mb2++) {
                mma_bf16(acc[mb2][nb], ah[mb2], bh2.x, bh2.y);
                mma_bf16(acc[mb2][nb], ah[mb2], bl2.x, bl2.y);
                mma_bf16(acc[mb2][nb], al[mb2], bh2.x, bh2.y);
            }
        }
    }
}

// ---------------- QKV projection: epilogue emits fragments directly -----
__global__ void __launch_bounds__(256, 2)
qkv_mma() {
    extern __shared__ unsigned gsm[];
    int mat = blockIdx.z;
    const unsigned* Bh = g_wh + (size_t)mat * WMAT_STRIDE;
    const unsigned* Bl = g_wl + (size_t)mat * WMAT_STRIDE;
    int m0 = blockIdx.y * 128, n0 = blockIdx.x * 128;
    float acc[2][8][4] = {};
    mma_gemm_bf16(g_xh, g_xl, Bh, Bl, m0 >> 4, n0 >> 3, acc, gsm);

    int lane = threadIdx.x & 31, wid = threadIdx.x >> 5;
    int warp_m = wid >> 1, warp_n = wid & 1;
    int g = lane >> 2, t = lane & 3;
    int hq = (n0 >> 6) + warp_n;          // head index 0..7
    #pragma unroll
    for (int mb2 = 0; mb2 < 2; mb2++) {
        int mbase = m0 + warp_m * 32 + mb2 * 16;   // multiple of 16
        int b = mbase >> 9, sbase = mbase & 511;
        int bh = b * NH + hq;
        if (mat == 0) {
            size_t base = (size_t)bh * 16384 + (size_t)(sbase >> 4) * 512;
            #pragma unroll
            for (int kb = 0; kb < 4; kb++) {
                unsigned hr[4], lr[4];
                #pragma unroll
                for (int r = 0; r < 4; r++) {
                    int nb = 2 * kb + (r >> 1), e = (r & 1) * 2;
                    float e0 = acc[mb2][nb][e], e1 = acc[mb2][nb][e + 1];
                    float h0 = bf16f(e0), h1 = bf16f(e1);
                    hr[r] = pk2(h0, h1);
                    lr[r] = pk2(e0 - h0, e1 - h1);
                }
                *(uint4*)&g_qfh[base + kb * 128 + lane * 4] = make_uint4(hr[0], hr[1], hr[2], hr[3]);
                *(uint4*)&g_qfl[base + kb * 128 + lane * 4] = make_uint4(lr[0], lr[1], lr[2], lr[3]);
            }
        } else if (mat == 1) {
            int nblk0 = sbase >> 3;
            #pragma unroll
            for (int kb = 0; kb < 4; kb++)
                #pragma unroll
                for (int j = 0; j < 2; j++) {
                    unsigned h0r, h1r, l0r, l1r;
                    {
                        float e0 = acc[mb2][2*kb][2*j], e1 = acc[mb2][2*kb][2*j+1];
                        float a0 = bf16f(e0), a1 = bf16f(e1);
                        h0r = pk2(a0, a1); l0r = pk2(e0 - a0, e1 - a1);
                    }
                    {
                        float e0 = acc[mb2][2*kb+1][2*j], e1 = acc[mb2][2*kb+1][2*j+1];
                        float a0 = bf16f(e0), a1 = bf16f(e1);
                        h1r = pk2(a0, a1); l1r = pk2(e0 - a0, e1 - a1);
                    }
                    size_t idx = (size_t)bh * 16384 + (size_t)kb * 4096 + (size_t)(nblk0 + j) * 64 + lane * 2;
                    *(uint2*)&g_kfh[idx] = make_uint2(h0r, h1r);
                    *(uint2*)&g_kfl[idx] = make_uint2(l0r, l1r);
                }
        } else {
            #pragma unroll
            for (int nb = 0; nb < 8; nb++) {
                int d = nb * 8 + 2 * t;
                *(float2*)&g_v[((size_t)bh * NS + sbase + g) * NDH + d] =
                    make_float2(acc[mb2][nb][0], acc[mb2][nb][1]);
                *(float2*)&g_v[((size_t)bh * NS + sbase + g + 8) * NDH + d] =
                    make_float2(acc[mb2][nb][2], acc[mb2][nb][3]);
            }
        }
    }
}

// ---------------- out = y @ Wo + bo ----------------
__global__ void __launch_bounds__(256, 2)
out_mma(const float* __restrict__ bo, float* __restrict__ out) {
    extern __shared__ unsigned gsm[];
    const unsigned* Bh = g_wh + (size_t)3 * WMAT_STRIDE;
    const unsigned* Bl = g_wl + (size_t)3 * WMAT_STRIDE;
    int m0 = blockIdx.y * 128, n0 = blockIdx.x * 128;
    float acc[2][8][4] = {};
    mma_gemm_bf16(g_yh, g_yl, Bh, Bl, m0 >> 4, n0 >> 3, acc, gsm);

    int lane = threadIdx.x & 31, wid = threadIdx.x >> 5;
    int warp_m = wid >> 1, warp_n = wid & 1;
    int g = lane >> 2, t = lane & 3;
    #pragma unroll
    for (int mb2 = 0; mb2 < 2; mb2++) {
        int mrow = m0 + warp_m * 32 + mb2 * 16 + g;
        #pragma unroll
        for (int nb = 0; nb < 8; nb++) {
            int ncol = n0 + (warp_n * 8 + nb) * 8 + 2 * t;
            float b0 = bo[ncol], b1 = bo[ncol + 1];
            *(float2*)&out[(size_t)mrow * NDIM + ncol] =
                make_float2(acc[mb2][nb][0] + b0, acc[mb2][nb][1] + b1);
            *(float2*)&out[(size_t)(mrow + 8) * NDIM + ncol] =
                make_float2(acc[mb2][nb][2] + b0, acc[mb2][nb][3] + b1);
        }
    }
}

// =====================================================================
// bf16 mma flash attention (unchanged from R14)
// =====================================================================
#define ATTN_SMEM_BYTES (4 * 2048 * 4 + 64 * 4)

__global__ void __launch_bounds__(128, 2)
attn_mma(const float* __restrict__ gate) {
    extern __shared__ unsigned smu[];
    unsigned* sKh = smu;
    unsigned* sKl = smu + 2048;
    unsigned* sVh = smu + 4096;
    unsigned* sVl = smu + 6144;
    float* opos_s = (float*)(smu + 8192);

    int tid = threadIdx.x, lane = tid & 31, w = tid >> 5;
    int bh = blockIdx.y, q0 = blockIdx.x * 64;
    int h = bh & 7, b = bh >> 3;
    int g = lane >> 2, t = lane & 3;
    int mblk = (q0 >> 4) + w;
    int rowbase = w * 16;

    float gv = 1.0f / (1.0f + __expf(-gate[h]));
    float og = 1.0f - gv;
    if (tid < 64) opos_s[tid] = g_opos[bh * NDH + tid];

    const unsigned* kfh = g_kfh + (size_t)bh * 16384;
    const unsigned* kfl = g_kfl + (size_t)bh * 16384;
    const unsigned* vfh = g_vfh + (size_t)bh * 16384;
    const unsigned* vfl = g_vfl + (size_t)bh * 16384;

    auto stage_K = [&](int kc) {
        #pragma unroll
        for (int r = 0; r < 4; r++) {
            int i = (r * 128 + tid) * 4;          // 0..2047
            int kb = i >> 9, rem = i & 511;
            size_t off = ((size_t)(kb * 64 + kc * 8)) * 64 + rem;
            CPA16(cvta_sh(&sKh[i]), kfh + off);
            CPA16(cvta_sh(&sKl[i]), kfl + off);
        }
        asm volatile("cp.async.commit_group;");
    };
    auto stage_V = [&](int kc) {
        #pragma unroll
        for (int r = 0; r < 4; r++) {
            int i = (r * 128 + tid) * 4;
            size_t off = (size_t)kc * 2048 + i;
            CPA16(cvta_sh(&sVh[i]), vfh + off);
            CPA16(cvta_sh(&sVl[i]), vfl + off);
        }
        asm volatile("cp.async.commit_group;");
    };

    // Q fragments hoisted
    unsigned aqh[4][4], aql[4][4];
    {
        const unsigned* qh = g_qfh + (size_t)bh * 16384 + (size_t)mblk * 512;
        const unsigned* ql = g_qfl + (size_t)bh * 16384 + (size_t)mblk * 512;
        #pragma unroll
        for (int kb = 0; kb < 4; kb++) {
            uint4 hv = *(const uint4*)&qh[kb * 128 + lane * 4];
            uint4 lv = *(const uint4*)&ql[kb * 128 + lane * 4];
            aqh[kb][0] = hv.x; aqh[kb][1] = hv.y; aqh[kb][2] = hv.z; aqh[kb][3] = hv.w;
            aql[kb][0] = lv.x; aql[kb][1] = lv.y; aql[kb][2] = lv.z; aql[kb][3] = lv.w;
        }
    }

    stage_K(0);
    stage_V(0);

    float o[8][4] = {};
    float mrow[2] = {-1e30f, -1e30f};
    float lrow[2] = {0.0f, 0.0f};

    for (int kc = 0; kc < 8; kc++) {
        asm volatile("cp.async.wait_group 1;");   // K(kc) ready
        __syncthreads();

        float sacc[8][4] = {};
        #pragma unroll
        for (int kb = 0; kb < 4; kb++) {
            #pragma unroll
            for (int nb = 0; nb < 8; nb++) {
                int off = kb * 512 + nb * 64 + lane * 2;
                uint2 bh2 = *(uint2*)&sKh[off];
                uint2 bl2 = *(uint2*)&sKl[off];
                mma_bf16(sacc[nb], aqh[kb], bh2.x, bh2.y);
                mma_bf16(sacc[nb], aqh[kb], bl2.x, bl2.y);
                mma_bf16(sacc[nb], aql[kb], bh2.x, bh2.y);
            }
        }
        __syncthreads();
        if (kc < 7) stage_K(kc + 1);

        // online softmax
        #pragma unroll
        for (int j = 0; j < 2; j++) {
            float mx = -1e30f;
            #pragma unroll
            for (int nb = 0; nb < 8; nb++)
                mx = fmaxf(mx, fmaxf(sacc[nb][2*j], sacc[nb][2*j+1]));
            mx *= 0.125f;
            mx = fmaxf(mx, __shfl_xor_sync(0xFFFFFFFF, mx, 1));
            mx = fmaxf(mx, __shfl_xor_sync(0xFFFFFFFF, mx, 2));
            float mn = fmaxf(mrow[j], mx);
            float alpha = __expf(mrow[j] - mn);
            float rs = 0.0f;
            #pragma unroll
            for (int nb = 0; nb < 8; nb++) {
                float p0 = __expf(sacc[nb][2*j] * 0.125f - mn);
                float p1 = __expf(sacc[nb][2*j+1] * 0.125f - mn);
                sacc[nb][2*j] = p0; sacc[nb][2*j+1] = p1;
                rs += p0 + p1;
            }
            rs += __shfl_xor_sync(0xFFFFFFFF, rs, 1);
            rs += __shfl_xor_sync(0xFFFFFFFF, rs, 2);
            lrow[j] = lrow[j] * alpha + rs;
            mrow[j] = mn;
            #pragma unroll
            for (int nb = 0; nb < 8; nb++) { o[nb][2*j] *= alpha; o[nb][2*j+1] *= alpha; }
        }

        asm volatile("cp.async.wait_group 1;");   // V(kc) ready
        __syncthreads();

        // O += P @ V, P fragments packed from registers
        #pragma unroll
        for (int kb = 0; kb < 4; kb++) {
            unsigned ph[4], pl[4];
            #pragma unroll
            for (int r = 0; r < 4; r++) {
                int nbp = 2 * kb + (r >> 1);
                int e = (r & 1) * 2;
                float e0 = sacc[nbp][e], e1 = sacc[nbp][e + 1];
                float h0 = bf16f(e0), h1 = bf16f(e1);
                ph[r] = pk2(h0, h1);
                pl[r] = pk2(e0 - h0, e1 - h1);
            }
            #pragma unroll
            for (int nb = 0; nb < 8; nb++) {
                int off = kb * 512 + nb * 64 + lane * 2;
                uint2 vh2 = *(uint2*)&sVh[off];
                uint2 vl2 = *(uint2*)&sVl[off];
                mma_bf16(o[nb], ph, vh2.x, vh2.y);
                mma_bf16(o[nb], ph, vl2.x, vl2.y);
                mma_bf16(o[nb], pl, vh2.x, vh2.y);
            }
        }
        __syncthreads();
        if (kc < 7) stage_V(kc + 1);
    }

    // epilogue: emit y A-fragments directly
    {
        int mblk_y = (b * NS + q0 + rowbase) >> 4;
        size_t ybase = (size_t)mblk_y * 4096 + (size_t)h * 512;
        float f0 = og / lrow[0], f1 = og / lrow[1];
        #pragma unroll
        for (int kb = 0; kb < 4; kb++) {
            unsigned hr[4], lr[4];
            #pragma unroll
            for (int r = 0; r < 4; r++) {
                int nb = 2 * kb + (r >> 1);
                int j = r & 1;
                float f = j ? f1 : f0;
                int d0 = nb * 8 + 2 * t;
                float e0 = o[nb][2*j]   * f + gv * opos_s[d0];
                float e1 = o[nb][2*j+1] * f + gv * opos_s[d0 + 1];
                float h0 = bf16f(e0), h1 = bf16f(e1);
                hr[r] = pk2(h0, h1);
                lr[r] = pk2(e0 - h0, e1 - h1);
            }
            *(uint4*)&g_yh[ybase + kb * 128 + lane * 4] = make_uint4(hr[0], hr[1], hr[2], hr[3]);
            *(uint4*)&g_yl[ybase + kb * 128 + lane * 4] = make_uint4(lr[0], lr[1], lr[2], lr[3]);
        }
    }
}

extern "C" void kernel_launch(void* const* d_in, const int* in_sizes, int n_in,
                              void* d_out, int out_size) {
    const float* x    = (const float*)d_in[0];
    const float* pos  = (const float*)d_in[1];
    const float* Wq   = (const float*)d_in[2];
    const float* Wk   = (const float*)d_in[3];
    const float* Wv   = (const float*)d_in[4];
    const float* Wo   = (const float*)d_in[5];
    const float* bo   = (const float*)d_in[6];
    const float* Wp1  = (const float*)d_in[7];
    const float* bp1  = (const float*)d_in[8];
    const float* Wp2  = (const float*)d_in[9];
    const float* bp2  = (const float*)d_in[10];
    const float* Wh   = (const float*)d_in[11];
    // d_in[12] = bh : cancels inside softmax — unused
    const float* gate = (const float*)d_in[13];
    float* out = (float*)d_out;

    static bool attr_set = false;
    if (!attr_set) {
        cudaFuncSetAttribute(attn_mma, cudaFuncAttributeMaxDynamicSharedMemorySize, ATTN_SMEM_BYTES);
        cudaFuncSetAttribute(qkv_mma, cudaFuncAttributeMaxDynamicSharedMemorySize, GEMM_SMEM_BYTES);
        cudaFuncSetAttribute(out_mma, cudaFuncAttributeMaxDynamicSharedMemorySize, GEMM_SMEM_BYTES);
        attr_set = true;
    }

    prep_kernel<<<1536, 256>>>(x, Wq, Wk, Wv, Wo);
    pos_w_kernel<<<32, 512>>>(pos, Wp1, bp1, Wp2, bp2, Wh);
    qkv_mma<<<dim3(4, 16, 3), 256, GEMM_SMEM_BYTES>>>();
    vprep_kernel<<<1152, 256>>>();
    attn_mma<<<dim3(8, 32), 128, ATTN_SMEM_BYTES>>>(gate);
    out_mma<<<dim3(4, 16), 256, GEMM_SMEM_BYTES>>>(bo, out);
}

// round 17
// speedup vs baseline: 2.2963x; 1.1151x over previous
#include <cuda_runtime.h>
#include <cuda_bf16.h>
#include <math.h>

#define NB 4
#define NS 512
#define NDIM 512
#define NH 8
#define NDH 64
#define NM (NB*NS)     // 2048

// ---------------- device scratch ----------------
__device__ float g_v[NB*NH*NS*NDH];     // [b][h][s][d] (opos consumes)
__device__ float g_w[NB*NH*NS];
__device__ float g_opos[NB*NH*NDH];

__device__ unsigned g_xh[NM*NDIM/2], g_xl[NM*NDIM/2];
__device__ unsigned g_yh[NM*NDIM/2], g_yl[NM*NDIM/2];
__device__ unsigned g_wh[4*NDIM*NDIM/2], g_wl[4*NDIM*NDIM/2];
#define WMAT_STRIDE (NDIM*NDIM/2)       // 131072
__device__ unsigned g_qfh[NB*NH*NS*NDH/2], g_qfl[NB*NH*NS*NDH/2];
__device__ unsigned g_kfh[NB*NH*NS*NDH/2], g_kfl[NB*NH*NS*NDH/2];
__device__ unsigned g_vfh[NB*NH*NS*NDH/2], g_vfl[NB*NH*NS*NDH/2];

__device__ __forceinline__ float bf16f(float x) {
    return __bfloat162float(__float2bfloat16_rn(x));
}
__device__ __forceinline__ unsigned pk2(float e0, float e1) {
    unsigned r;
    asm("cvt.rn.bf16x2.f32 %0, %1, %2;" : "=r"(r) : "f"(e1), "f"(e0));
    return r;
}

__device__ __forceinline__ void mma_bf16(float (&d)[4], const unsigned (&a)[4],
                                         unsigned b0, unsigned b1) {
    asm volatile(
        "mma.sync.aligned.m16n8k16.row.col.f32.bf16.bf16.f32 "
        "{%0,%1,%2,%3}, {%4,%5,%6,%7}, {%8,%9}, {%0,%1,%2,%3};"
        : "+f"(d[0]), "+f"(d[1]), "+f"(d[2]), "+f"(d[3])
        : "r"(a[0]), "r"(a[1]), "r"(a[2]), "r"(a[3]), "r"(b0), "r"(b1));
}

__device__ __forceinline__ unsigned cvta_sh(const void* p) {
    return (unsigned)__cvta_generic_to_shared(p);
}
#define CPA16(dst, src) \
    asm volatile("cp.async.cg.shared.global [%0], [%1], 16;" :: "r"(dst), "l"(src))

// ---------------- fused prep: split_w (0..1023) + split_x (1024..1535) ----
__global__ void prep_kernel(const float* __restrict__ X,
                            const float* __restrict__ Wq, const float* __restrict__ Wk,
                            const float* __restrict__ Wv, const float* __restrict__ Wo) {
    int lane = threadIdx.x & 31;
    int g = lane >> 2, t = lane & 3;
    if (blockIdx.x < 1024) {
        int gw = blockIdx.x * 8 + (threadIdx.x >> 5);
        int mat = gw >> 11, rem = gw & 2047;
        const float* W = (mat == 0) ? Wq : (mat == 1) ? Wk : (mat == 2) ? Wv : Wo;
        int kblk = rem >> 6, nblk = rem & 63;
        unsigned hr[2], lr[2];
        #pragma unroll
        for (int r = 0; r < 2; r++) {
            int k = kblk * 16 + 2 * t + r * 8;
            int n = nblk * 8 + g;
            float v0 = W[k * NDIM + n], v1 = W[(k + 1) * NDIM + n];
            float h0 = bf16f(v0), h1 = bf16f(v1);
            hr[r] = pk2(h0, h1);
            lr[r] = pk2(v0 - h0, v1 - h1);
        }
        size_t idx = (size_t)mat * WMAT_STRIDE + ((size_t)rem * 32 + lane) * 2;
        *(uint2*)&g_wh[idx] = make_uint2(hr[0], hr[1]);
        *(uint2*)&g_wl[idx] = make_uint2(lr[0], lr[1]);
    } else {
        int gw = (blockIdx.x - 1024) * 8 + (threadIdx.x >> 5);
        int mblk = gw >> 5, kblk = gw & 31;
        unsigned hr[4], lr[4];
        #pragma unroll
        for (int r = 0; r < 4; r++) {
            int row = mblk * 16 + g + (r & 1) * 8;
            int col = kblk * 16 + 2 * t + (r >> 1) * 8;
            float2 v = *(const float2*)&X[row * NDIM + col];
            float h0 = bf16f(v.x), h1 = bf16f(v.y);
            hr[r] = pk2(h0, h1);
            lr[r] = pk2(v.x - h0, v.y - h1);
        }
        size_t idx = ((size_t)gw * 32 + lane) * 4;
        *(uint4*)&g_xh[idx] = make_uint4(hr[0], hr[1], hr[2], hr[3]);
        *(uint4*)&g_xl[idx] = make_uint4(lr[0], lr[1], lr[2], lr[3]);
    }
}

// ---------------- fused positional path ----------------
__global__ void pos_w_kernel(const float* __restrict__ pos,
                             const float* __restrict__ Wp1, const float* __restrict__ bp1,
                             const float* __restrict__ Wp2, const float* __restrict__ bp2,
                             const float* __restrict__ Wh) {
    __shared__ float red[512];
    int bh = blockIdx.x;
    int b = bh >> 3, h = bh & 7;
    int k = threadIdx.x;
    if (k < 64) g_opos[bh * NDH + k] = 0.0f;
    const float* pp = pos + ((size_t)b * NS + k) * 3;
    float p0 = pp[0], p1 = pp[1], p2 = pp[2];
    float h1[3];
    #pragma unroll
    for (int j = 0; j < 3; j++)
        h1[j] = fmaxf(0.0f, p0 * Wp1[j] + p1 * Wp1[3 + j] + p2 * Wp1[6 + j] + bp1[j]);
    float u = 0.0f;
    for (int j = 0; j < 64; j++) {
        float pv = h1[0] * Wp2[j] + h1[1] * Wp2[64 + j] + h1[2] * Wp2[128 + j] + bp2[j];
        u += pv * Wh[j * NH + h];
    }
    float t = -u;
    red[k] = t; __syncthreads();
    for (int s = 256; s > 0; s >>= 1) { if (k < s) red[k] = fmaxf(red[k], red[k + s]); __syncthreads(); }
    float m = red[0]; __syncthreads();
    float e = expf(t - m);
    red[k] = e; __syncthreads();
    for (int s = 256; s > 0; s >>= 1) { if (k < s) red[k] += red[k + s]; __syncthreads(); }
    g_w[bh * NS + k] = e / red[0];
}

// ---------------- opos only (split_v fused into qkv) ----------------
__global__ void opos_kernel() {
    __shared__ float part[4][64];
    int bh = blockIdx.x >> 2, kq = blockIdx.x & 3;
    int d = threadIdx.x & 63;
    int ks = threadIdx.x >> 6;
    const float* V = g_v + (size_t)bh * NS * NDH;
    const float* w = g_w + bh * NS;
    int kbase = kq * 128 + ks * 32;
    float s = 0.0f;
    #pragma unroll 4
    for (int k = kbase; k < kbase + 32; k++)
        s += w[k] * V[k * NDH + d];
    part[ks][d] = s;
    __syncthreads();
    if (threadIdx.x < 64)
        atomicAdd(&g_opos[bh * NDH + d], part[0][d] + part[1][d] + part[2][d] + part[3][d]);
}

// =====================================================================
// bf16 x3 MMA GEMM core, 128x128 tile (qkv).
// =====================================================================
#define GEMM_SMEM_BYTES (3 * 4096 * 4)   // 49152

__device__ __forceinline__ void mma_gemm_bf16(const unsigned* __restrict__ Ah,
                                              const unsigned* __restrict__ Al,
                                              const unsigned* __restrict__ Bh,
                                              const unsigned* __restrict__ Bl,
                                              int mblk0, int nblk0,
                                              float (&acc)[2][8][4], unsigned* sm) {
    int tid = threadIdx.x, lane = tid & 31, wid = tid >> 5;
    int warp_m = wid >> 1, warp_n = wid & 1;
    int a_mb = tid >> 5, a_ln = tid & 31;
    int b_nb = tid >> 4, b_j = tid & 15;

    const unsigned* srcAh = Ah + (size_t)(mblk0 + a_mb) * 4096 + a_ln * 4;
    const unsigned* srcAl = Al + (size_t)(mblk0 + a_mb) * 4096 + a_ln * 4;
    const unsigned* srcBh = Bh + (size_t)(nblk0 + b_nb) * 64 + b_j * 4;
    const unsigned* srcBl = Bl + (size_t)(nblk0 + b_nb) * 64 + b_j * 4;

    auto issue = [&](int s) {
        unsigned* base = sm + (s % 3) * 4096;
        CPA16(cvta_sh(base + a_mb * 128 + a_ln * 4),        srcAh + s * 128);
        CPA16(cvta_sh(base + 1024 + a_mb * 128 + a_ln * 4), srcAl + s * 128);
        CPA16(cvta_sh(base + 2048 + b_nb * 64 + b_j * 4),   srcBh + (size_t)s * 4096);
        CPA16(cvta_sh(base + 3072 + b_nb * 64 + b_j * 4),   srcBl + (size_t)s * 4096);
        asm volatile("cp.async.commit_group;");
    };

    issue(0);
    issue(1);
    for (int s = 0; s < 32; s++) {
        if (s < 31) asm volatile("cp.async.wait_group 1;");
        else        asm volatile("cp.async.wait_group 0;");
        __syncthreads();
        if (s < 30) issue(s + 2);
        unsigned* base = sm + (s % 3) * 4096;
        unsigned ah[2][4], al[2][4];
        #pragma unroll
        for (int mb2 = 0; mb2 < 2; mb2++) {
            uint4 h4 = *(uint4*)(base + (warp_m * 2 + mb2) * 128 + lane * 4);
            uint4 l4 = *(uint4*)(base + 1024 + (warp_m * 2 + mb2) * 128 + lane * 4);
            ah[mb2][0] = h4.x; ah[mb2][1] = h4.y; ah[mb2][2] = h4.z; ah[mb2][3] = h4.w;
            al[mb2][0] = l4.x; al[mb2][1] = l4.y; al[mb2][2] = l4.z; al[mb2][3] = l4.w;
        }
        #pragma unroll
        for (int nb = 0; nb < 8; nb++) {
            uint2 bh2 = *(uint2*)(base + 2048 + (warp_n * 8 + nb) * 64 + lane * 2);
            uint2 bl2 = *(uint2*)(base + 3072 + (warp_n * 8 + nb) * 64 + lane * 2);
            #pragma unroll
            for (int mb2 = 0; mb2 < 2; mb2++) {
                mma_bf16(acc[mb2][nb], ah[mb2], bh2.x, bh2.y);
                mma_bf16(acc[mb2][nb], ah[mb2], bl2.x, bl2.y);
                mma_bf16(acc[mb2][nb], al[mb2], bh2.x, bh2.y);
            }
        }
    }
}

// ---------------- QKV projection: fragment-emitting epilogues ----------
__global__ void __launch_bounds__(256, 2)
qkv_mma() {
    extern __shared__ unsigned gsm[];
    int mat = blockIdx.z;
    const unsigned* Bh = g_wh + (size_t)mat * WMAT_STRIDE;
    const unsigned* Bl = g_wl + (size_t)mat * WMAT_STRIDE;
    int m0 = blockIdx.y * 128, n0 = blockIdx.x * 128;
    float acc[2][8][4] = {};
    mma_gemm_bf16(g_xh, g_xl, Bh, Bl, m0 >> 4, n0 >> 3, acc, gsm);

    int tid = threadIdx.x;
    int lane = tid & 31, wid = tid >> 5;
    int warp_m = wid >> 1, warp_n = wid & 1;
    int g = lane >> 2, t = lane & 3;
    int hq = (n0 >> 6) + warp_n;
    #pragma unroll
    for (int mb2 = 0; mb2 < 2; mb2++) {
        int mbase = m0 + warp_m * 32 + mb2 * 16;
        int b = mbase >> 9, sbase = mbase & 511;
        int bh = b * NH + hq;
        if (mat == 0) {
            size_t base = (size_t)bh * 16384 + (size_t)(sbase >> 4) * 512;
            #pragma unroll
            for (int kb = 0; kb < 4; kb++) {
                unsigned hr[4], lr[4];
                #pragma unroll
                for (int r = 0; r < 4; r++) {
                    int nb = 2 * kb + (r >> 1), e = (r & 1) * 2;
                    float e0 = acc[mb2][nb][e], e1 = acc[mb2][nb][e + 1];
                    float h0 = bf16f(e0), h1 = bf16f(e1);
                    hr[r] = pk2(h0, h1);
                    lr[r] = pk2(e0 - h0, e1 - h1);
                }
                *(uint4*)&g_qfh[base + kb * 128 + lane * 4] = make_uint4(hr[0], hr[1], hr[2], hr[3]);
                *(uint4*)&g_qfl[base + kb * 128 + lane * 4] = make_uint4(lr[0], lr[1], lr[2], lr[3]);
            }
        } else if (mat == 1) {
            int nblk0 = sbase >> 3;
            #pragma unroll
            for (int kb = 0; kb < 4; kb++)
                #pragma unroll
                for (int j = 0; j < 2; j++) {
                    unsigned h0r, h1r, l0r, l1r;
                    {
                        float e0 = acc[mb2][2*kb][2*j], e1 = acc[mb2][2*kb][2*j+1];
                        float a0 = bf16f(e0), a1 = bf16f(e1);
                        h0r = pk2(a0, a1); l0r = pk2(e0 - a0, e1 - a1);
                    }
                    {
                        float e0 = acc[mb2][2*kb+1][2*j], e1 = acc[mb2][2*kb+1][2*j+1];
                        float a0 = bf16f(e0), a1 = bf16f(e1);
                        h1r = pk2(a0, a1); l1r = pk2(e0 - a0, e1 - a1);
                    }
                    size_t idx = (size_t)bh * 16384 + (size_t)kb * 4096 + (size_t)(nblk0 + j) * 64 + lane * 2;
                    *(uint2*)&g_kfh[idx] = make_uint2(h0r, h1r);
                    *(uint2*)&g_kfl[idx] = make_uint2(l0r, l1r);
                }
        } else {
            // V: float stores for opos
            #pragma unroll
            for (int nb = 0; nb < 8; nb++) {
                int d = nb * 8 + 2 * t;
                *(float2*)&g_v[((size_t)bh * NS + sbase + g) * NDH + d] =
                    make_float2(acc[mb2][nb][0], acc[mb2][nb][1]);
                *(float2*)&g_v[((size_t)bh * NS + sbase + g + 8) * NDH + d] =
                    make_float2(acc[mb2][nb][2], acc[mb2][nb][3]);
            }
        }
    }

    // ---- fused split_v: smem fp32 transpose, emit V B-fragments ----
    if (mat == 2) {
        float* fs = (float*)gsm;               // 64 x 132 fp32 = 33.8KB < 48KB
        int b = m0 >> 9;
        int kpb_base = (m0 & 511) >> 4;
        #pragma unroll
        for (int p = 0; p < 2; p++) {
            __syncthreads();
            if ((warp_m >> 1) == p) {
                #pragma unroll
                for (int mb2 = 0; mb2 < 2; mb2++) {
                    int rowloc = (warp_m & 1) * 32 + mb2 * 16 + g;
                    #pragma unroll
                    for (int nb = 0; nb < 8; nb++) {
                        int col = (warp_n * 8 + nb) * 8 + 2 * t;
                        fs[rowloc * 132 + col]     = acc[mb2][nb][0];
                        fs[rowloc * 132 + col + 1] = acc[mb2][nb][1];
                        fs[(rowloc + 8) * 132 + col]     = acc[mb2][nb][2];
                        fs[(rowloc + 8) * 132 + col + 1] = acc[mb2][nb][3];
                    }
                }
            }
            __syncthreads();
            // emit fragments for local rows [0,64): 2048 slots, 8/thread
            #pragma unroll
            for (int i = 0; i < 8; i++) {
                int gid = i * 256 + tid;            // 0..2047
                int lane_f = gid & 31;
                int nblk_f = (gid >> 5) & 7;
                int kpbl = (gid >> 8) & 3;
                int hq_l = gid >> 10;               // 0..1
                int t_f = lane_f & 3, g_f = lane_f >> 2;
                int col = hq_l * 64 + nblk_f * 8 + g_f;
                int k0 = kpbl * 16 + 2 * t_f;
                float v00 = fs[k0 * 132 + col];
                float v01 = fs[(k0 + 1) * 132 + col];
                float v10 = fs[(k0 + 8) * 132 + col];
                float v11 = fs[(k0 + 9) * 132 + col];
                float h00 = bf16f(v00), h01 = bf16f(v01);
                float h10 = bf16f(v10), h11 = bf16f(v11);
                int bh_f = b * NH + (n0 >> 6) + hq_l;
                int kpb_g = kpb_base + p * 4 + kpbl;
                size_t idx = (size_t)bh_f * 16384 + (size_t)kpb_g * 512
                           + (size_t)nblk_f * 64 + lane_f * 2;
                *(uint2*)&g_vfh[idx] = make_uint2(pk2(h00, h01), pk2(h10, h11));
                *(uint2*)&g_vfl[idx] = make_uint2(pk2(v00 - h00, v01 - h01),
                                                  pk2(v10 - h10, v11 - h11));
            }
        }
    }
}

// =====================================================================
// out = y @ Wo + bo : 128x64 tiles, grid (8,16) = 128 CTAs.
// stage = 3072 u32: Ah[1024] Al[1024] Bh[512] Bl[512]; 3 buffers = 36KB
// =====================================================================
#define OUT_SMEM_BYTES (3 * 3072 * 4)   // 36864

__global__ void __launch_bounds__(256, 2)
out_mma(const float* __restrict__ bo, float* __restrict__ out) {
    extern __shared__ unsigned gsm[];
    const unsigned* BhG = g_wh + (size_t)3 * WMAT_STRIDE;
    const unsigned* BlG = g_wl + (size_t)3 * WMAT_STRIDE;
    int m0 = blockIdx.y * 128, n0 = blockIdx.x * 64;
    int mblk0 = m0 >> 4, nblk0 = n0 >> 3;

    int tid = threadIdx.x, lane = tid & 31, wid = tid >> 5;
    int warp_m = wid >> 1, warp_n = wid & 1;
    int a_mb = tid >> 5, a_ln = tid & 31;
    int bu = tid & 127;
    int b_nb = bu >> 4, b_j = bu & 15;
    const unsigned* srcAh = g_yh + (size_t)(mblk0 + a_mb) * 4096 + a_ln * 4;
    const unsigned* srcAl = g_yl + (size_t)(mblk0 + a_mb) * 4096 + a_ln * 4;
    const unsigned* srcB  = ((tid < 128) ? BhG : BlG) + (size_t)(nblk0 + b_nb) * 64 + b_j * 4;
    unsigned bofs = (tid < 128) ? 2048u : 2560u;

    float acc[2][4][4] = {};

    auto issue = [&](int s) {
        unsigned* base = gsm + (s % 3) * 3072;
        CPA16(cvta_sh(base + a_mb * 128 + a_ln * 4),        srcAh + s * 128);
        CPA16(cvta_sh(base + 1024 + a_mb * 128 + a_ln * 4), srcAl + s * 128);
        CPA16(cvta_sh(base + bofs + b_nb * 64 + b_j * 4),   srcB + (size_t)s * 4096);
        asm volatile("cp.async.commit_group;");
    };

    issue(0);
    issue(1);
    for (int s = 0; s < 32; s++) {
        if (s < 31) asm volatile("cp.async.wait_group 1;");
        else        asm volatile("cp.async.wait_group 0;");
        __syncthreads();
        if (s < 30) issue(s + 2);
        unsigned* base = gsm + (s % 3) * 3072;
        unsigned ah[2][4], al[2][4];
        #pragma unroll
        for (int mb2 = 0; mb2 < 2; mb2++) {
            uint4 h4 = *(uint4*)(base + (warp_m * 2 + mb2) * 128 + lane * 4);
            uint4 l4 = *(uint4*)(base + 1024 + (warp_m * 2 + mb2) * 128 + lane * 4);
            ah[mb2][0] = h4.x; ah[mb2][1] = h4.y; ah[mb2][2] = h4.z; ah[mb2][3] = h4.w;
            al[mb2][0] = l4.x; al[mb2][1] = l4.y; al[mb2][2] = l4.z; al[mb2][3] = l4.w;
        }
        #pragma unroll
        for (int nb = 0; nb < 4; nb++) {
            uint2 bh2 = *(uint2*)(base + 2048 + (warp_n * 4 + nb) * 64 + lane * 2);
            uint2 bl2 = *(uint2*)(base + 2560 + (warp_n * 4 + nb) * 64 + lane * 2);
            #pragma unroll
            for (int mb2 = 0; mb2 < 2; mb2++) {
                mma_bf16(acc[mb2][nb], ah[mb2], bh2.x, bh2.y);
                mma_bf16(acc[mb2][nb], ah[mb2], bl2.x, bl2.y);
                mma_bf16(acc[mb2][nb], al[mb2], bh2.x, bh2.y);
            }
        }
    }

    int g = lane >> 2, t = lane & 3;
    #pragma unroll
    for (int mb2 = 0; mb2 < 2; mb2++) {
        int mrow = m0 + warp_m * 32 + mb2 * 16 + g;
        #pragma unroll
        for (int nb = 0; nb < 4; nb++) {
            int ncol = n0 + (warp_n * 4 + nb) * 8 + 2 * t;
            float b0 = bo[ncol], b1 = bo[ncol + 1];
            *(float2*)&out[(size_t)mrow * NDIM + ncol] =
                make_float2(acc[mb2][nb][0] + b0, acc[mb2][nb][1] + b1);
            *(float2*)&out[(size_t)(mrow + 8) * NDIM + ncol] =
                make_float2(acc[mb2][nb][2] + b0, acc[mb2][nb][3] + b1);
        }
    }
}

// =====================================================================
// bf16 mma flash attention (unchanged from R15)
// =====================================================================
#define ATTN_SMEM_BYTES (4 * 2048 * 4 + 64 * 4)

__global__ void __launch_bounds__(128, 2)
attn_mma(const float* __restrict__ gate) {
    extern __shared__ unsigned smu[];
    unsigned* sKh = smu;
    unsigned* sKl = smu + 2048;
    unsigned* sVh = smu + 4096;
    unsigned* sVl = smu + 6144;
    float* opos_s = (float*)(smu + 8192);

    int tid = threadIdx.x, lane = tid & 31, w = tid >> 5;
    int bh = blockIdx.y, q0 = blockIdx.x * 64;
    int h = bh & 7, b = bh >> 3;
    int g = lane >> 2, t = lane & 3;
    int mblk = (q0 >> 4) + w;
    int rowbase = w * 16;

    float gv = 1.0f / (1.0f + __expf(-gate[h]));
    float og = 1.0f - gv;
    if (tid < 64) opos_s[tid] = g_opos[bh * NDH + tid];

    const unsigned* kfh = g_kfh + (size_t)bh * 16384;
    const unsigned* kfl = g_kfl + (size_t)bh * 16384;
    const unsigned* vfh = g_vfh + (size_t)bh * 16384;
    const unsigned* vfl = g_vfl + (size_t)bh * 16384;

    auto stage_K = [&](int kc) {
        #pragma unroll
        for (int r = 0; r < 4; r++) {
            int i = (r * 128 + tid) * 4;
            int kb = i >> 9, rem = i & 511;
            size_t off = ((size_t)(kb * 64 + kc * 8)) * 64 + rem;
            CPA16(cvta_sh(&sKh[i]), kfh + off);
            CPA16(cvta_sh(&sKl[i]), kfl + off);
        }
        asm volatile("cp.async.commit_group;");
    };
    auto stage_V = [&](int kc) {
        #pragma unroll
        for (int r = 0; r < 4; r++) {
            int i = (r * 128 + tid) * 4;
            size_t off = (size_t)kc * 2048 + i;
            CPA16(cvta_sh(&sVh[i]), vfh + off);
            CPA16(cvta_sh(&sVl[i]), vfl + off);
        }
        asm volatile("cp.async.commit_group;");
    };

    unsigned aqh[4][4], aql[4][4];
    {
        const unsigned* qh = g_qfh + (size_t)bh * 16384 + (size_t)mblk * 512;
        const unsigned* ql = g_qfl + (size_t)bh * 16384 + (size_t)mblk * 512;
        #pragma unroll
        for (int kb = 0; kb < 4; kb++) {
            uint4 hv = *(const uint4*)&qh[kb * 128 + lane * 4];
            uint4 lv = *(const uint4*)&ql[kb * 128 + lane * 4];
            aqh[kb][0] = hv.x; aqh[kb][1] = hv.y; aqh[kb][2] = hv.z; aqh[kb][3] = hv.w;
            aql[kb][0] = lv.x; aql[kb][1] = lv.y; aql[kb][2] = lv.z; aql[kb][3] = lv.w;
        }
    }

    stage_K(0);
    stage_V(0);

    float o[8][4] = {};
    float mrow[2] = {-1e30f, -1e30f};
    float lrow[2] = {0.0f, 0.0f};

    for (int kc = 0; kc < 8; kc++) {
        asm volatile("cp.async.wait_group 1;");
        __syncthreads();

        float sacc[8][4] = {};
        #pragma unroll
        for (int kb = 0; kb < 4; kb++) {
            #pragma unroll
            for (int nb = 0; nb < 8; nb++) {
                int off = kb * 512 + nb * 64 + lane * 2;
                uint2 bh2 = *(uint2*)&sKh[off];
                uint2 bl2 = *(uint2*)&sKl[off];
                mma_bf16(sacc[nb], aqh[kb], bh2.x, bh2.y);
                mma_bf16(sacc[nb], aqh[kb], bl2.x, bl2.y);
                mma_bf16(sacc[nb], aql[kb], bh2.x, bh2.y);
            }
        }
        __syncthreads();
        if (kc < 7) stage_K(kc + 1);

        #pragma unroll
        for (int j = 0; j < 2; j++) {
            float mx = -1e30f;
            #pragma unroll
            for (int nb = 0; nb < 8; nb++)
                mx = fmaxf(mx, fmaxf(sacc[nb][2*j], sacc[nb][2*j+1]));
            mx *= 0.125f;
            mx = fmaxf(mx, __shfl_xor_sync(0xFFFFFFFF, mx, 1));
            mx = fmaxf(mx, __shfl_xor_sync(0xFFFFFFFF, mx, 2));
            float mn = fmaxf(mrow[j], mx);
            float alpha = __expf(mrow[j] - mn);
            float rs = 0.0f;
            #pragma unroll
            for (int nb = 0; nb < 8; nb++) {
                float p0 = __expf(sacc[nb][2*j] * 0.125f - mn);
                float p1 = __expf(sacc[nb][2*j+1] * 0.125f - mn);
                sacc[nb][2*j] = p0; sacc[nb][2*j+1] = p1;
                rs += p0 + p1;
            }
            rs += __shfl_xor_sync(0xFFFFFFFF, rs, 1);
            rs += __shfl_xor_sync(0xFFFFFFFF, rs, 2);
            lrow[j] = lrow[j] * alpha + rs;
            mrow[j] = mn;
            #pragma unroll
            for (int nb = 0; nb < 8; nb++) { o[nb][2*j] *= alpha; o[nb][2*j+1] *= alpha; }
        }

        asm volatile("cp.async.wait_group 1;");
        __syncthreads();

        #pragma unroll
        for (int kb = 0; kb < 4; kb++) {
            unsigned ph[4], pl[4];
            #pragma unroll
            for (int r = 0; r < 4; r++) {
                int nbp = 2 * kb + (r >> 1);
                int e = (r & 1) * 2;
                float e0 = sacc[nbp][e], e1 = sacc[nbp][e + 1];
                float h0 = bf16f(e0), h1 = bf16f(e1);
                ph[r] = pk2(h0, h1);
                pl[r] = pk2(e0 - h0, e1 - h1);
            }
            #pragma unroll
            for (int nb = 0; nb < 8; nb++) {
                int off = kb * 512 + nb * 64 + lane * 2;
                uint2 vh2 = *(uint2*)&sVh[off];
                uint2 vl2 = *(uint2*)&sVl[off];
                mma_bf16(o[nb], ph, vh2.x, vh2.y);
                mma_bf16(o[nb], ph, vl2.x, vl2.y);
                mma_bf16(o[nb], pl, vh2.x, vh2.y);
            }
        }
        __syncthreads();
        if (kc < 7) stage_V(kc + 1);
    }

    {
        int mblk_y = (b * NS + q0 + rowbase) >> 4;
        size_t ybase = (size_t)mblk_y * 4096 + (size_t)h * 512;
        float f0 = og / lrow[0], f1 = og / lrow[1];
        #pragma unroll
        for (int kb = 0; kb < 4; kb++) {
            unsigned hr[4], lr[4];
            #pragma unroll
            for (int r = 0; r < 4; r++) {
                int nb = 2 * kb + (r >> 1);
                int j = r & 1;
                float f = j ? f1 : f0;
                int d0 = nb * 8 + 2 * t;
                float e0 = o[nb][2*j]   * f + gv * opos_s[d0];
                float e1 = o[nb][2*j+1] * f + gv * opos_s[d0 + 1];
                float h0 = bf16f(e0), h1 = bf16f(e1);
                hr[r] = pk2(h0, h1);
                lr[r] = pk2(e0 - h0, e1 - h1);
            }
            *(uint4*)&g_yh[ybase + kb * 128 + lane * 4] = make_uint4(hr[0], hr[1], hr[2], hr[3]);
            *(uint4*)&g_yl[ybase + kb * 128 + lane * 4] = make_uint4(lr[0], lr[1], lr[2], lr[3]);
        }
    }
}

extern "C" void kernel_launch(void* const* d_in, const int* in_sizes, int n_in,
                              void* d_out, int out_size) {
    const float* x    = (const float*)d_in[0];
    const float* pos  = (const float*)d_in[1];
    const float* Wq   = (const float*)d_in[2];
    const float* Wk   = (const float*)d_in[3];
    const float* Wv   = (const float*)d_in[4];
    const float* Wo   = (const float*)d_in[5];
    const float* bo   = (const float*)d_in[6];
    const float* Wp1  = (const float*)d_in[7];
    const float* bp1  = (const float*)d_in[8];
    const float* Wp2  = (const float*)d_in[9];
    const float* bp2  = (const float*)d_in[10];
    const float* Wh   = (const float*)d_in[11];
    // d_in[12] = bh : cancels inside softmax — unused
    const float* gate = (const float*)d_in[13];
    float* out = (float*)d_out;

    static bool attr_set = false;
    if (!attr_set) {
        cudaFuncSetAttribute(attn_mma, cudaFuncAttributeMaxDynamicSharedMemorySize, ATTN_SMEM_BYTES);
        cudaFuncSetAttribute(qkv_mma, cudaFuncAttributeMaxDynamicSharedMemorySize, GEMM_SMEM_BYTES);
        cudaFuncSetAttribute(out_mma, cudaFuncAttributeMaxDynamicSharedMemorySize, OUT_SMEM_BYTES);
        attr_set = true;
    }

    prep_kernel<<<1536, 256>>>(x, Wq, Wk, Wv, Wo);
    pos_w_kernel<<<32, 512>>>(pos, Wp1, bp1, Wp2, bp2, Wh);
    qkv_mma<<<dim3(4, 16, 3), 256, GEMM_SMEM_BYTES>>>();
    opos_kernel<<<128, 256>>>();
    attn_mma<<<dim3(8, 32), 128, ATTN_SMEM_BYTES>>>(gate);
    out_mma<<<dim3(8, 16), 256, OUT_SMEM_BYTES>>>(bo, out);
}